// round 13
// baseline (speedup 1.0000x reference)
#include <cuda_runtime.h>
#include <cuda_bf16.h>
#include <cstdint>

typedef unsigned long long ull;
typedef __nv_bfloat16 bf16;

#define NN 20000
#define NE 320000
#define ET (NE+NN)
#define BB 128
#define TT 200

__device__ __forceinline__ ull fma2(ull a, ull b, ull c){
  ull d; asm("fma.rn.f32x2 %0, %1, %2, %3;" : "=l"(d) : "l"(a), "l"(b), "l"(c)); return d;
}
__device__ __forceinline__ float hsum2(ull v){
  float lo, hi; asm("mov.b64 {%0, %1}, %2;" : "=f"(lo), "=f"(hi) : "l"(v)); return lo + hi;
}
__device__ __forceinline__ float sigf(float x){ return 1.f/(1.f+__expf(-x)); }

__device__ __forceinline__ void bsplit(float x, bf16* h, bf16* l){
  bf16 hb = __float2bfloat16(x);
  *h = hb;
  *l = __float2bfloat16(x - __bfloat162float(hb));
}

#define MMA_BF16(C, A, B) \
  asm volatile("mma.sync.aligned.m16n8k16.row.col.f32.bf16.bf16.f32 " \
    "{%0,%1,%2,%3}, {%4,%5,%6,%7}, {%8,%9}, {%0,%1,%2,%3};" \
    : "+f"((C)[0]), "+f"((C)[1]), "+f"((C)[2]), "+f"((C)[3]) \
    : "r"((A)[0]), "r"((A)[1]), "r"((A)[2]), "r"((A)[3]), "r"((B)[0]), "r"((B)[1]))

// ---------------- scratch (device globals; no allocs) ----------------
__device__ float g_h1[NN*256];
__device__ float g_h2[NN*128];
__device__ float g_as1[NN*4];
__device__ float g_ad1[NN*4];
__device__ float g_as2[NN];
__device__ float g_ad2[NN];
__device__ int   g_cnt[NN];
__device__ int   g_fill[NN];
__device__ int   g_rowptr[NN+1];
__device__ int   g_srcs[ET];
__device__ float g_xproj[2][(size_t)BB*TT*512];
__device__ float g_lstm[BB*TT*256];
__device__ float g_ctx[2][BB*256];
__device__ int   g_aidxf[BB*TT];
__device__ int   g_aidxb[BB*TT];
__device__ int   g_cidx[BB*TT];
__device__ int   g_mc;
__device__ int   g_perm[BB];
// bf16 split operand buffers
__device__ bf16 g_nfh[NN*144],  g_nfl[NN*144];     // A1 [N][144]
__device__ bf16 g_w1h[256*144], g_w1l[256*144];    // B1^T [256][144]
__device__ bf16 g_z1h[NN*256],  g_z1l[NN*256];     // A2 [N][256]
__device__ bf16 g_w2h[128*256], g_w2l[128*256];    // B2^T [128][256]
__device__ bf16 g_z2h[NN*128],  g_z2l[NN*128];     // Ax [N][128]
__device__ bf16 g_wih[2][2][512*128];              // [dir][hi/lo] Bx^T [512][128]
__device__ bf16 g_cxh[BB*256],  g_cxl[BB*256];     // Afc [128][256]

// ---------------- prep: nf bf16 split, wih splits ----------------
__global__ void k_prep(const float* __restrict__ xc, const float* __restrict__ tf,
                       const float* __restrict__ emb,
                       const float* __restrict__ wihf, const float* __restrict__ wihb){
  int i = blockIdx.x*256 + threadIdx.x;
  if (i < NN*144){
    int r = i/144, c = i - r*144;
    float v = 0.f;
    if (c < 2)        v = xc[r*2 + c];
    else if (c < 130) v = emb[r*128 + (c-2)];
    else if (c < 134) v = tf[r*4 + (c-130)];
    bsplit(v, &g_nfh[i], &g_nfl[i]);
  }
  if (i < 512*128){
    bsplit(wihf[i], &g_wih[0][0][i], &g_wih[0][1][i]);
    bsplit(wihb[i], &g_wih[1][0][i], &g_wih[1][1][i]);
  }
}

// ---------------- transpose + bf16 split: src[Ks][Ns] -> dst[Ns][Kp] ----------------
__global__ void k_tsplit(const float* __restrict__ src, bf16* __restrict__ dh,
                         bf16* __restrict__ dl, int Ks, int Ns, int Kp){
  __shared__ float t[32][33];
  int n0 = blockIdx.x*32, k0 = blockIdx.y*32;
  int tx = threadIdx.x, ty = threadIdx.y;
  int k = k0 + ty, n = n0 + tx;
  t[ty][tx] = (k < Ks && n < Ns) ? src[(size_t)k*Ns + n] : 0.f;
  __syncthreads();
  int nn = n0 + ty, kk = k0 + tx;
  if (nn < Ns && kk < Kp){
    float v = t[tx][ty];
    bsplit(v, &dh[(size_t)nn*Kp + kk], &dl[(size_t)nn*Kp + kk]);
  }
}

// ---------------- compact valid (b,t) rows + length-sorted batch permutation ----------------
__global__ void k_seqidx(const int* __restrict__ seq, const int* __restrict__ lengths){
  __shared__ int red[256];
  int b = blockIdx.x, tid = threadIdx.x;
  red[tid] = (tid < b) ? lengths[tid] : 0;
  __syncthreads();
  #pragma unroll
  for (int o = 128; o; o >>= 1){ if (tid < o) red[tid] += red[tid+o]; __syncthreads(); }
  int off = red[0];
  int len = lengths[b];
  for (int t = tid; t < len; t += 256){
    g_aidxf[off+t] = seq[b*TT + t];
    g_aidxb[off+t] = seq[b*TT + (len-1-t)];
    g_cidx[off+t]  = b*TT + t;
  }
  if (b == BB-1 && tid == 0) g_mc = off + len;
  // descending-length permutation (deterministic; block 0, lanes < BB)
  if (b == 0 && tid < BB){
    int li = lengths[tid];
    int rank = 0;
    for (int j = 0; j < BB; j++){
      int lj = lengths[j];
      if (lj > li || (lj == li && j < tid)) rank++;
    }
    g_perm[rank] = tid;
  }
}

// ---------------- CSR build ----------------
__global__ void k_zero_cnt(){
  int i = blockIdx.x*256 + threadIdx.x;
  if (i < NN){ g_cnt[i] = 0; g_fill[i] = 0; }
}
__global__ void k_count(const int* __restrict__ ei){
  int e = blockIdx.x*256 + threadIdx.x;
  if (e >= ET) return;
  int d = (e < NE) ? ei[NE + e] : (e - NE);
  atomicAdd(&g_cnt[d], 1);
}
__global__ void k_scan(){
  __shared__ int ps[1024];
  int tid = threadIdx.x;
  int base = tid*20;
  int sum = 0;
  for (int j = 0; j < 20; j++){ int i = base + j; if (i < NN) sum += g_cnt[i]; }
  ps[tid] = sum;
  __syncthreads();
  for (int off = 1; off < 1024; off <<= 1){
    int v = (tid >= off) ? ps[tid-off] : 0;
    __syncthreads();
    ps[tid] += v;
    __syncthreads();
  }
  int run = ps[tid] - sum;
  for (int j = 0; j < 20; j++){ int i = base + j; if (i < NN){ g_rowptr[i] = run; run += g_cnt[i]; } }
  if (tid == 0) g_rowptr[NN] = ET;
}
__global__ void k_scatter(const int* __restrict__ ei){
  int e = blockIdx.x*256 + threadIdx.x;
  if (e >= ET) return;
  int d = (e < NE) ? ei[NE + e] : (e - NE);
  int p = atomicAdd(&g_fill[d], 1);
  g_srcs[g_rowptr[d] + p] = e;
}
__global__ void k_sortseg(const int* __restrict__ ei){
  __shared__ int buf[8][128];
  int wid = threadIdx.x >> 5, lane = threadIdx.x & 31;
  int n = blockIdx.x*8 + wid;
  if (n >= NN) return;
  int r0 = g_rowptr[n], r1 = g_rowptr[n+1], d = r1 - r0;
  if (d <= 128){
    for (int j = lane; j < d; j += 32) buf[wid][j] = g_srcs[r0 + j];
    __syncwarp();
    if (lane == 0){
      for (int a = 1; a < d; a++){
        int v = buf[wid][a]; int b = a - 1;
        while (b >= 0 && buf[wid][b] > v){ buf[wid][b+1] = buf[wid][b]; b--; }
        buf[wid][b+1] = v;
      }
    }
    __syncwarp();
    for (int j = lane; j < d; j += 32){
      int id = buf[wid][j];
      g_srcs[r0 + j] = (id < NE) ? ei[id] : (id - NE);
    }
  } else {
    for (int j = lane; j < d; j += 32){
      int id = g_srcs[r0 + j];
      g_srcs[r0 + j] = (id < NE) ? ei[id] : (id - NE);
    }
  }
}

// ---- bf16-split HMMA GEMM (proven version): C[128x64] = A(hi,lo)@B^T(hi,lo) ----
__global__ void __launch_bounds__(256, 2)
k_hgemm(const bf16* __restrict__ Ah, const bf16* __restrict__ Al,
        const bf16* __restrict__ Bh, const bf16* __restrict__ Bl,
        const float* __restrict__ bias, float* __restrict__ C,
        int M, int Ntot, int K,
        const int* __restrict__ Aidx, const int* __restrict__ Cidx, int useMc){
  __shared__ bf16 sAh[128][24], sAl[128][24], sBh[64][24], sBl[64][24];
  int tid = threadIdx.x, warp = tid >> 5, lane = tid & 31;
  int Mr = useMc ? g_mc : M;
  int bm = blockIdx.y*128;
  if (bm >= Mr) return;
  int bn = blockIdx.x*64;
  int wm = (warp >> 1)*32, wn = (warp & 1)*32;

  float c[2][4][4];
  #pragma unroll
  for (int mi = 0; mi < 2; mi++)
    #pragma unroll
    for (int ni = 0; ni < 4; ni++)
      #pragma unroll
      for (int q = 0; q < 4; q++) c[mi][ni][q] = 0.f;

  int arow = tid >> 1, au = (tid & 1) << 3;
  int grA = bm + arow;
  const bf16* pAh = nullptr; const bf16* pAl = nullptr;
  if (grA < Mr){
    int src = Aidx ? Aidx[grA] : grA;
    pAh = Ah + (size_t)src*K;
    pAl = Al + (size_t)src*K;
  }
  int brow = (tid & 127) >> 1, bu = (tid & 1) << 3;
  bool bhi = tid < 128;
  int gnB = bn + brow;
  const bf16* pB = nullptr;
  if (gnB < Ntot) pB = (bhi ? Bh : Bl) + (size_t)gnB*K;

  int nk = K >> 4;
  uint4 zz = make_uint4(0,0,0,0);
  uint4 vAh = zz, vAl = zz, vB = zz;
  if (pAh){ vAh = *(const uint4*)(pAh + au); vAl = *(const uint4*)(pAl + au); }
  if (pB)  vB  = *(const uint4*)(pB + bu);
  *(uint4*)&sAh[arow][au] = vAh;
  *(uint4*)&sAl[arow][au] = vAl;
  if (bhi) *(uint4*)&sBh[brow][bu] = vB; else *(uint4*)&sBl[brow][bu] = vB;
  __syncthreads();

  int r = lane >> 2, kq = (lane & 3) << 1;
  for (int kc = 0; kc < nk; kc++){
    bool more = (kc + 1 < nk);
    if (more){
      int k0 = (kc + 1) << 4;
      vAh = zz; vAl = zz; vB = zz;
      if (pAh){ vAh = *(const uint4*)(pAh + k0 + au); vAl = *(const uint4*)(pAl + k0 + au); }
      if (pB)  vB  = *(const uint4*)(pB + k0 + bu);
    }
    uint32_t fah[2][4], fal[2][4], fbh[4][2], fbl[4][2];
    #pragma unroll
    for (int mi = 0; mi < 2; mi++){
      int rb = wm + mi*16 + r;
      fah[mi][0] = *(const uint32_t*)&sAh[rb  ][kq];
      fah[mi][1] = *(const uint32_t*)&sAh[rb+8][kq];
      fah[mi][2] = *(const uint32_t*)&sAh[rb  ][kq+8];
      fah[mi][3] = *(const uint32_t*)&sAh[rb+8][kq+8];
      fal[mi][0] = *(const uint32_t*)&sAl[rb  ][kq];
      fal[mi][1] = *(const uint32_t*)&sAl[rb+8][kq];
      fal[mi][2] = *(const uint32_t*)&sAl[rb  ][kq+8];
      fal[mi][3] = *(const uint32_t*)&sAl[rb+8][kq+8];
    }
    #pragma unroll
    for (int ni = 0; ni < 4; ni++){
      int nb = wn + ni*8 + r;
      fbh[ni][0] = *(const uint32_t*)&sBh[nb][kq];
      fbh[ni][1] = *(const uint32_t*)&sBh[nb][kq+8];
      fbl[ni][0] = *(const uint32_t*)&sBl[nb][kq];
      fbl[ni][1] = *(const uint32_t*)&sBl[nb][kq+8];
    }
    #pragma unroll
    for (int mi = 0; mi < 2; mi++)
      #pragma unroll
      for (int ni = 0; ni < 4; ni++){
        MMA_BF16(c[mi][ni], fah[mi], fbh[ni]);
        MMA_BF16(c[mi][ni], fah[mi], fbl[ni]);
        MMA_BF16(c[mi][ni], fal[mi], fbh[ni]);
      }
    if (more){
      __syncthreads();
      *(uint4*)&sAh[arow][au] = vAh;
      *(uint4*)&sAl[arow][au] = vAl;
      if (bhi) *(uint4*)&sBh[brow][bu] = vB; else *(uint4*)&sBl[brow][bu] = vB;
      __syncthreads();
    }
  }

  #pragma unroll
  for (int mi = 0; mi < 2; mi++){
    #pragma unroll
    for (int ni = 0; ni < 4; ni++){
      int col = bn + wn + ni*8 + kq;
      if (col >= Ntot) continue;
      float bx = 0.f, by = 0.f;
      if (bias){ bx = bias[col]; by = bias[col+1]; }
      int row0 = bm + wm + mi*16 + r;
      if (row0 < Mr){
        int cr = Cidx ? Cidx[row0] : row0;
        float2 v = make_float2(c[mi][ni][0] + bx, c[mi][ni][1] + by);
        *(float2*)(C + (size_t)cr*Ntot + col) = v;
      }
      if (row0 + 8 < Mr){
        int cr = Cidx ? Cidx[row0+8] : row0+8;
        float2 v = make_float2(c[mi][ni][2] + bx, c[mi][ni][3] + by);
        *(float2*)(C + (size_t)cr*Ntot + col) = v;
      }
    }
  }
}

// ---- fc_node HMMA GEMM: B read directly from f32 [K][N] (fnW), split on the fly ----
__global__ void __launch_bounds__(256, 2)
k_hgemm_fcn(const bf16* __restrict__ Ah, const bf16* __restrict__ Al,
            const float* __restrict__ Bf, const float* __restrict__ bias,
            float* __restrict__ C, int M, int Ntot, int K){
  __shared__ bf16 sAh[128][24], sAl[128][24], sBh[64][24], sBl[64][24];
  int tid = threadIdx.x, warp = tid >> 5, lane = tid & 31;
  int bm = 0;
  int bn = blockIdx.x*64;
  int wm = (warp >> 1)*32, wn = (warp & 1)*32;

  float c[2][4][4];
  #pragma unroll
  for (int mi = 0; mi < 2; mi++)
    #pragma unroll
    for (int ni = 0; ni < 4; ni++)
      #pragma unroll
      for (int q = 0; q < 4; q++) c[mi][ni][q] = 0.f;

  int arow = tid >> 1, au = (tid & 1) << 3;
  const bf16* pAh = Ah + (size_t)arow*K;
  const bf16* pAl = Al + (size_t)arow*K;
  int bk = tid >> 4, bn4 = (tid & 15) << 2;
  bool bok = (bn + bn4 < Ntot);

  int nk = K >> 4;
  uint4 vAh, vAl;
  float4 vB = make_float4(0.f,0.f,0.f,0.f);
  vAh = *(const uint4*)(pAh + au);
  vAl = *(const uint4*)(pAl + au);
  if (bok) vB = *(const float4*)(Bf + (size_t)bk*Ntot + bn + bn4);
  *(uint4*)&sAh[arow][au] = vAh;
  *(uint4*)&sAl[arow][au] = vAl;
  {
    float bvals[4] = {vB.x, vB.y, vB.z, vB.w};
    #pragma unroll
    for (int i = 0; i < 4; i++)
      bsplit(bvals[i], &sBh[bn4 + i][bk], &sBl[bn4 + i][bk]);
  }
  __syncthreads();

  int r = lane >> 2, kq = (lane & 3) << 1;
  for (int kc = 0; kc < nk; kc++){
    bool more = (kc + 1 < nk);
    if (more){
      int k0 = (kc + 1) << 4;
      vAh = *(const uint4*)(pAh + k0 + au);
      vAl = *(const uint4*)(pAl + k0 + au);
      vB = make_float4(0.f,0.f,0.f,0.f);
      if (bok) vB = *(const float4*)(Bf + (size_t)(k0 + bk)*Ntot + bn + bn4);
    }
    uint32_t fah[2][4], fal[2][4], fbh[4][2], fbl[4][2];
    #pragma unroll
    for (int mi = 0; mi < 2; mi++){
      int rb = wm + mi*16 + r;
      fah[mi][0] = *(const uint32_t*)&sAh[rb  ][kq];
      fah[mi][1] = *(const uint32_t*)&sAh[rb+8][kq];
      fah[mi][2] = *(const uint32_t*)&sAh[rb  ][kq+8];
      fah[mi][3] = *(const uint32_t*)&sAh[rb+8][kq+8];
      fal[mi][0] = *(const uint32_t*)&sAl[rb  ][kq];
      fal[mi][1] = *(const uint32_t*)&sAl[rb+8][kq];
      fal[mi][2] = *(const uint32_t*)&sAl[rb  ][kq+8];
      fal[mi][3] = *(const uint32_t*)&sAl[rb+8][kq+8];
    }
    #pragma unroll
    for (int ni = 0; ni < 4; ni++){
      int nb = wn + ni*8 + r;
      fbh[ni][0] = *(const uint32_t*)&sBh[nb][kq];
      fbh[ni][1] = *(const uint32_t*)&sBh[nb][kq+8];
      fbl[ni][0] = *(const uint32_t*)&sBl[nb][kq];
      fbl[ni][1] = *(const uint32_t*)&sBl[nb][kq+8];
    }
    #pragma unroll
    for (int mi = 0; mi < 2; mi++)
      #pragma unroll
      for (int ni = 0; ni < 4; ni++){
        MMA_BF16(c[mi][ni], fah[mi], fbh[ni]);
        MMA_BF16(c[mi][ni], fah[mi], fbl[ni]);
        MMA_BF16(c[mi][ni], fal[mi], fbh[ni]);
      }
    if (more){
      __syncthreads();
      *(uint4*)&sAh[arow][au] = vAh;
      *(uint4*)&sAl[arow][au] = vAl;
      float bvals[4] = {vB.x, vB.y, vB.z, vB.w};
      #pragma unroll
      for (int i = 0; i < 4; i++)
        bsplit(bvals[i], &sBh[bn4 + i][bk], &sBl[bn4 + i][bk]);
      __syncthreads();
    }
  }

  #pragma unroll
  for (int mi = 0; mi < 2; mi++){
    #pragma unroll
    for (int ni = 0; ni < 4; ni++){
      int col = bn + wn + ni*8 + kq;
      if (col >= Ntot) continue;
      float bx = bias[col], by = bias[col+1];
      int row0 = bm + wm + mi*16 + r;
      float2 v0 = make_float2(c[mi][ni][0] + bx, c[mi][ni][1] + by);
      *(float2*)(C + (size_t)row0*Ntot + col) = v0;
      float2 v1 = make_float2(c[mi][ni][2] + bx, c[mi][ni][3] + by);
      *(float2*)(C + (size_t)(row0+8)*Ntot + col) = v1;
    }
  }
}

// ---------------- scalar SGEMM (fc_sp only) ----------------
__global__ void k_gemm(const float* __restrict__ A, const float* __restrict__ B,
                       const float* __restrict__ bias, float* __restrict__ C,
                       int M, int N, int K){
  __shared__ float As[16][64];
  __shared__ float Bs[16][64];
  int bn = blockIdx.x*64, bm = blockIdx.y*64;
  int tid = threadIdx.x;
  int tx = tid & 15, ty = tid >> 4;
  float acc[4][4];
  #pragma unroll
  for (int i = 0; i < 4; i++)
    #pragma unroll
    for (int j = 0; j < 4; j++) acc[i][j] = 0.f;
  int ar = tid >> 2, ak = (tid & 3) << 2;
  int bk = tid >> 4, bn2 = (tid & 15) << 2;
  for (int k0 = 0; k0 < K; k0 += 16){
    float4 av = make_float4(0.f,0.f,0.f,0.f);
    if (bm + ar < M) av = *(const float4*)(A + (size_t)(bm + ar)*K + k0 + ak);
    As[ak  ][ar] = av.x; As[ak+1][ar] = av.y; As[ak+2][ar] = av.z; As[ak+3][ar] = av.w;
    float4 bv = make_float4(0.f,0.f,0.f,0.f);
    if (bn + bn2 < N) bv = *(const float4*)(B + (size_t)(k0 + bk)*N + bn + bn2);
    *(float4*)&Bs[bk][bn2] = bv;
    __syncthreads();
    #pragma unroll
    for (int kk = 0; kk < 16; kk++){
      float4 ra = *(const float4*)&As[kk][ty << 2];
      float4 rb = *(const float4*)&Bs[kk][tx << 2];
      acc[0][0] += ra.x*rb.x; acc[0][1] += ra.x*rb.y; acc[0][2] += ra.x*rb.z; acc[0][3] += ra.x*rb.w;
      acc[1][0] += ra.y*rb.x; acc[1][1] += ra.y*rb.y; acc[1][2] += ra.y*rb.z; acc[1][3] += ra.y*rb.w;
      acc[2][0] += ra.z*rb.x; acc[2][1] += ra.z*rb.y; acc[2][2] += ra.z*rb.z; acc[2][3] += ra.z*rb.w;
      acc[3][0] += ra.w*rb.x; acc[3][1] += ra.w*rb.y; acc[3][2] += ra.w*rb.z; acc[3][3] += ra.w*rb.w;
    }
    __syncthreads();
  }
  #pragma unroll
  for (int i = 0; i < 4; i++){
    int row = bm + (ty << 2) + i;
    if (row >= M) continue;
    #pragma unroll
    for (int j = 0; j < 4; j++){
      int col = bn + (tx << 2) + j;
      if (col >= N) continue;
      float v = acc[i][j];
      if (bias) v += bias[col];
      C[(size_t)row*N + col] = v;
    }
  }
}

// ---------------- attention dots ----------------
__global__ void k_attdot1(const float* __restrict__ aw_s, const float* __restrict__ aw_d){
  int i = blockIdx.x*256 + threadIdx.x;
  if (i >= NN*4) return;
  int n = i >> 2, h = i & 3;
  const float4* hp = (const float4*)(g_h1 + n*256 + h*64);
  const float4* sw = (const float4*)(aw_s + h*64);
  const float4* dw = (const float4*)(aw_d + h*64);
  float s = 0.f, d = 0.f;
  #pragma unroll
  for (int j = 0; j < 16; j++){
    float4 x = hp[j], a = sw[j], b = dw[j];
    s += x.x*a.x + x.y*a.y + x.z*a.z + x.w*a.w;
    d += x.x*b.x + x.y*b.y + x.z*b.z + x.w*b.w;
  }
  g_as1[i] = s; g_ad1[i] = d;
}
__global__ void k_attdot2(const float* __restrict__ aw_s, const float* __restrict__ aw_d){
  int n = blockIdx.x*256 + threadIdx.x;
  if (n >= NN) return;
  const float4* hp = (const float4*)(g_h2 + n*128);
  const float4* sw = (const float4*)aw_s;
  const float4* dw = (const float4*)aw_d;
  float s = 0.f, d = 0.f;
  #pragma unroll
  for (int j = 0; j < 32; j++){
    float4 x = hp[j], a = sw[j], b = dw[j];
    s += x.x*a.x + x.y*a.y + x.z*a.z + x.w*a.w;
    d += x.x*b.x + x.y*b.y + x.z*b.z + x.w*b.w;
  }
  g_as2[n] = s; g_ad2[n] = d;
}

// ---------------- edge softmax + aggregation, layer 1 -> z1 bf16 split ----------------
__global__ void k_agg1(const float* __restrict__ bias){
  int wid = threadIdx.x >> 5, lane = threadIdx.x & 31;
  int n = blockIdx.x*8 + wid;
  int r0 = g_rowptr[n], r1 = g_rowptr[n+1];
  float4 ad = *(const float4*)(g_ad1 + n*4);
  float m0 = -1e30f, m1 = -1e30f, m2 = -1e30f, m3 = -1e30f;
  for (int e = r0 + lane; e < r1; e += 32){
    int s = g_srcs[e];
    float4 as = *(const float4*)(g_as1 + s*4);
    float v0 = as.x + ad.x; v0 = v0 > 0.f ? v0 : 0.2f*v0;
    float v1 = as.y + ad.y; v1 = v1 > 0.f ? v1 : 0.2f*v1;
    float v2 = as.z + ad.z; v2 = v2 > 0.f ? v2 : 0.2f*v2;
    float v3 = as.w + ad.w; v3 = v3 > 0.f ? v3 : 0.2f*v3;
    m0 = fmaxf(m0, v0); m1 = fmaxf(m1, v1); m2 = fmaxf(m2, v2); m3 = fmaxf(m3, v3);
  }
  #pragma unroll
  for (int o = 16; o; o >>= 1){
    m0 = fmaxf(m0, __shfl_xor_sync(0xffffffffu, m0, o));
    m1 = fmaxf(m1, __shfl_xor_sync(0xffffffffu, m1, o));
    m2 = fmaxf(m2, __shfl_xor_sync(0xffffffffu, m2, o));
    m3 = fmaxf(m3, __shfl_xor_sync(0xffffffffu, m3, o));
  }
  float s0 = 0.f, s1 = 0.f, s2 = 0.f, s3 = 0.f;
  for (int e = r0 + lane; e < r1; e += 32){
    int s = g_srcs[e];
    float4 as = *(const float4*)(g_as1 + s*4);
    float v0 = as.x + ad.x; v0 = v0 > 0.f ? v0 : 0.2f*v0;
    float v1 = as.y + ad.y; v1 = v1 > 0.f ? v1 : 0.2f*v1;
    float v2 = as.z + ad.z; v2 = v2 > 0.f ? v2 : 0.2f*v2;
    float v3 = as.w + ad.w; v3 = v3 > 0.f ? v3 : 0.2f*v3;
    s0 += __expf(v0 - m0); s1 += __expf(v1 - m1);
    s2 += __expf(v2 - m2); s3 += __expf(v3 - m3);
  }
  #pragma unroll
  for (int o = 16; o; o >>= 1){
    s0 += __shfl_xor_sync(0xffffffffu, s0, o);
    s1 += __shfl_xor_sync(0xffffffffu, s1, o);
    s2 += __shfl_xor_sync(0xffffffffu, s2, o);
    s3 += __shfl_xor_sync(0xffffffffu, s3, o);
  }
  int hsel = lane >> 3;
  float mh  = hsel == 0 ? m0 : hsel == 1 ? m1 : hsel == 2 ? m2 : m3;
  float inv = 1.f / (hsel == 0 ? s0 : hsel == 1 ? s1 : hsel == 2 ? s2 : s3);
  float adh = hsel == 0 ? ad.x : hsel == 1 ? ad.y : hsel == 2 ? ad.z : ad.w;
  float a0=0,a1=0,a2=0,a3=0,a4=0,a5=0,a6=0,a7=0;
  for (int e = r0; e < r1; e++){
    int s = g_srcs[e];
    float v = g_as1[s*4 + hsel] + adh; v = v > 0.f ? v : 0.2f*v;
    float alpha = __expf(v - mh) * inv;
    const float4* xp = (const float4*)(g_h1 + s*256 + lane*8);
    float4 x0 = xp[0], x1 = xp[1];
    a0 += alpha*x0.x; a1 += alpha*x0.y; a2 += alpha*x0.z; a3 += alpha*x0.w;
    a4 += alpha*x1.x; a5 += alpha*x1.y; a6 += alpha*x1.z; a7 += alpha*x1.w;
  }
  int cb = lane*8;
  float r[8] = {a0,a1,a2,a3,a4,a5,a6,a7};
  #pragma unroll
  for (int i = 0; i < 8; i++){
    float o = r[i] + bias[cb + i];
    o = o > 0.f ? o : expm1f(o);                           // ELU
    bsplit(o, &g_z1h[n*256 + cb + i], &g_z1l[n*256 + cb + i]);
  }
}

// ---------------- edge softmax + aggregation, layer 2 -> z2 bf16 split ----------------
__global__ void k_agg2(const float* __restrict__ bias){
  int wid = threadIdx.x >> 5, lane = threadIdx.x & 31;
  int n = blockIdx.x*8 + wid;
  int r0 = g_rowptr[n], r1 = g_rowptr[n+1];
  float ad = g_ad2[n];
  float m = -1e30f;
  for (int e = r0 + lane; e < r1; e += 32){
    float v = g_as2[g_srcs[e]] + ad; v = v > 0.f ? v : 0.2f*v;
    m = fmaxf(m, v);
  }
  #pragma unroll
  for (int o = 16; o; o >>= 1) m = fmaxf(m, __shfl_xor_sync(0xffffffffu, m, o));
  float ssum = 0.f;
  for (int e = r0 + lane; e < r1; e += 32){
    float v = g_as2[g_srcs[e]] + ad; v = v > 0.f ? v : 0.2f*v;
    ssum += __expf(v - m);
  }
  #pragma unroll
  for (int o = 16; o; o >>= 1) ssum += __shfl_xor_sync(0xffffffffu, ssum, o);
  float inv = 1.f / ssum;
  float a0=0,a1=0,a2=0,a3=0;
  for (int e = r0; e < r1; e++){
    int s = g_srcs[e];
    float v = g_as2[s] + ad; v = v > 0.f ? v : 0.2f*v;
    float alpha = __expf(v - m) * inv;
    float4 x = *(const float4*)(g_h2 + s*128 + lane*4);
    a0 += alpha*x.x; a1 += alpha*x.y; a2 += alpha*x.z; a3 += alpha*x.w;
  }
  int cb = lane*4;
  float rr[4] = {a0 + bias[cb], a1 + bias[cb+1], a2 + bias[cb+2], a3 + bias[cb+3]};
  #pragma unroll
  for (int i = 0; i < 4; i++)
    bsplit(rr[i], &g_z2h[n*128 + cb + i], &g_z2l[n*128 + cb + i]);
}

// ---------------- BiLSTM recurrence (length-sorted batch pairing) ----------------
__global__ void __launch_bounds__(512, 1)
k_lstm(const float* __restrict__ whhf, const float* __restrict__ whhb,
       const int* __restrict__ lengths){
  extern __shared__ char smraw[];
  ull*   ws  = (ull*)smraw;
  float* hsm = (float*)(ws + 512*33);
  float* gsm = hsm + 256;
  int g   = threadIdx.x;
  int dir = blockIdx.y;
  int ba = g_perm[blockIdx.x*2];
  int bbx = g_perm[blockIdx.x*2 + 1];
  const float* whh = dir ? whhb : whhf;
  const ull* wrow = (const ull*)(whh + g*128);
  ull wreg[32];
  #pragma unroll
  for (int j = 0; j < 32; j++) wreg[j] = wrow[j];
  #pragma unroll
  for (int j = 0; j < 32; j++) ws[g*33 + j] = wrow[32 + j];
  if (g < 256) hsm[g] = 0.f;
  float cc = 0.f;
  int len0 = lengths[ba], len1 = lengths[bbx];
  int Tn = len0 > len1 ? len0 : len1;
  const float* x0p = g_xproj[dir] + (size_t)ba*TT*512;
  const float* x1p = g_xproj[dir] + (size_t)bbx*TT*512;
  __syncthreads();
  for (int t = 0; t < Tn; t++){
    float xv0 = x0p[t*512 + g];
    float xv1 = x1p[t*512 + g];
    ull a0 = 0ULL, a1 = 0ULL;
    const ull* h0p = (const ull*)hsm;
    const ull* h1p = (const ull*)(hsm + 128);
    #pragma unroll
    for (int j = 0; j < 32; j++){
      ull w = wreg[j];
      a0 = fma2(w, h0p[j], a0);
      a1 = fma2(w, h1p[j], a1);
    }
    #pragma unroll
    for (int j = 0; j < 32; j++){
      ull w = ws[g*33 + j];
      a0 = fma2(w, h0p[32 + j], a0);
      a1 = fma2(w, h1p[32 + j], a1);
    }
    gsm[g]       = hsum2(a0) + xv0;
    gsm[512 + g] = hsum2(a1) + xv1;
    __syncthreads();
    if (g < 256){
      int b = g >> 7, j = g & 127;
      const float* gb = gsm + b*512;
      float gi = gb[j], gf = gb[128 + j], gg = gb[256 + j], go = gb[384 + j];
      cc = sigf(gf)*cc + sigf(gi)*tanhf(gg);
      float h = sigf(go)*tanhf(cc);
      hsm[b*128 + j] = h;
      int bt = b ? bbx : ba;
      int L = b ? len1 : len0;
      if (dir == 0){
        if (t < L) g_lstm[((size_t)bt*TT + t)*256 + j] = h;
      } else {
        if (t < L) g_lstm[((size_t)bt*TT + (L - 1 - t))*256 + 128 + j] = h;
      }
    }
    __syncthreads();
  }
}

// ---------------- masked attention pooling ----------------
__global__ void k_attnpool(const float* __restrict__ wn, const float* __restrict__ bn,
                           const float* __restrict__ wsp, const float* __restrict__ bsp,
                           const int* __restrict__ lengths){
  __shared__ float sc[256];
  __shared__ float red[256];
  int b = blockIdx.x, p = blockIdx.y;
  const float* w = p ? wsp : wn;
  float bias = p ? bsp[0] : bn[0];
  int tid = threadIdx.x;
  int len = lengths[b];
  float sv = -1e30f;
  if (tid < TT && tid < len){
    const float4* row = (const float4*)(g_lstm + ((size_t)b*TT + tid)*256);
    const float4* wv = (const float4*)w;
    float s = 0.f;
    #pragma unroll
    for (int j = 0; j < 64; j++){
      float4 x = row[j], y = wv[j];
      s += x.x*y.x + x.y*y.y + x.z*y.z + x.w*y.w;
    }
    sv = s + bias;
  }
  red[tid] = sv;
  __syncthreads();
  #pragma unroll
  for (int o = 128; o; o >>= 1){ if (tid < o) red[tid] = fmaxf(red[tid], red[tid+o]); __syncthreads(); }
  float m = red[0];
  __syncthreads();
  float e = (sv <= -1e29f) ? 0.f : __expf(sv - m);
  sc[tid] = e; red[tid] = e;
  __syncthreads();
  #pragma unroll
  for (int o = 128; o; o >>= 1){ if (tid < o) red[tid] += red[tid+o]; __syncthreads(); }
  float inv = 1.f / red[0];
  float acc = 0.f;
  for (int t = 0; t < TT; t++)
    acc += sc[t] * g_lstm[((size_t)b*TT + t)*256 + tid];
  float v = acc * inv;
  g_ctx[p][b*256 + tid] = v;
  if (p == 0) bsplit(v, &g_cxh[b*256 + tid], &g_cxl[b*256 + tid]);
}

// ---------------- launch ----------------
extern "C" void kernel_launch(void* const* d_in, const int* in_sizes, int n_in,
                              void* d_out, int out_size){
  const float* xc   = (const float*)d_in[0];
  const float* tf   = (const float*)d_in[1];
  const float* emb  = (const float*)d_in[2];
  const float* g1W  = (const float*)d_in[3];
  const float* g1as = (const float*)d_in[4];
  const float* g1ad = (const float*)d_in[5];
  const float* g1b  = (const float*)d_in[6];
  const float* g2W  = (const float*)d_in[7];
  const float* g2as = (const float*)d_in[8];
  const float* g2ad = (const float*)d_in[9];
  const float* g2b  = (const float*)d_in[10];
  const float* wihf = (const float*)d_in[11];
  const float* whhf = (const float*)d_in[12];
  const float* bf   = (const float*)d_in[13];
  const float* wihb = (const float*)d_in[14];
  const float* whhb = (const float*)d_in[15];
  const float* bb   = (const float*)d_in[16];
  const float* anw  = (const float*)d_in[17];
  const float* anb  = (const float*)d_in[18];
  const float* asw  = (const float*)d_in[19];
  const float* asb  = (const float*)d_in[20];
  const float* fnW  = (const float*)d_in[21];
  const float* fnb  = (const float*)d_in[22];
  const float* fsW  = (const float*)d_in[23];
  const float* fsb  = (const float*)d_in[24];
  const int*   ei   = (const int*)d_in[25];
  const int*   seq  = (const int*)d_in[26];
  const int*   len  = (const int*)d_in[27];
  float* out = (float*)d_out;

  float *p_h1, *p_h2, *p_xp, *p_ctx, *p_lstm;
  int *p_af, *p_ab, *p_ci;
  bf16 *p_nfh, *p_nfl, *p_w1h, *p_w1l, *p_z1h, *p_z1l, *p_w2h, *p_w2l;
  bf16 *p_z2h, *p_z2l, *p_wih, *p_cxh, *p_cxl;
  cudaGetSymbolAddress((void**)&p_h1,  g_h1);
  cudaGetSymbolAddress((void**)&p_h2,  g_h2);
  cudaGetSymbolAddress((void**)&p_xp,  g_xproj);
  cudaGetSymbolAddress((void**)&p_ctx, g_ctx);
  cudaGetSymbolAddress((void**)&p_lstm, g_lstm);
  cudaGetSymbolAddress((void**)&p_af,  g_aidxf);
  cudaGetSymbolAddress((void**)&p_ab,  g_aidxb);
  cudaGetSymbolAddress((void**)&p_ci,  g_cidx);
  cudaGetSymbolAddress((void**)&p_nfh, g_nfh);
  cudaGetSymbolAddress((void**)&p_nfl, g_nfl);
  cudaGetSymbolAddress((void**)&p_w1h, g_w1h);
  cudaGetSymbolAddress((void**)&p_w1l, g_w1l);
  cudaGetSymbolAddress((void**)&p_z1h, g_z1h);
  cudaGetSymbolAddress((void**)&p_z1l, g_z1l);
  cudaGetSymbolAddress((void**)&p_w2h, g_w2h);
  cudaGetSymbolAddress((void**)&p_w2l, g_w2l);
  cudaGetSymbolAddress((void**)&p_z2h, g_z2h);
  cudaGetSymbolAddress((void**)&p_z2l, g_z2l);
  cudaGetSymbolAddress((void**)&p_wih, g_wih);
  cudaGetSymbolAddress((void**)&p_cxh, g_cxh);
  cudaGetSymbolAddress((void**)&p_cxl, g_cxl);

  int lstm_smem = 512*33*8 + 256*4 + 1024*4;
  cudaFuncSetAttribute(k_lstm, cudaFuncAttributeMaxDynamicSharedMemorySize, lstm_smem);

  // index 3 (overall ncu launch #5) = GAT1 HMMA GEMM
  k_prep<<<11250, 256>>>(xc, tf, emb, wihf, wihb);                            // 0
  k_tsplit<<<dim3(8, 5),  dim3(32,32)>>>(g1W, p_w1h, p_w1l, 134, 256, 144);   // 1
  k_tsplit<<<dim3(4, 8),  dim3(32,32)>>>(g2W, p_w2h, p_w2l, 256, 128, 256);   // 2
  k_hgemm<<<dim3(4, 157), 256>>>(p_nfh, p_nfl, p_w1h, p_w1l,
      nullptr, p_h1, NN, 256, 144, nullptr, nullptr, 0);                      // 3 <- profiled
  k_zero_cnt<<<(NN+255)/256, 256>>>();
  k_count<<<(ET+255)/256, 256>>>(ei);
  k_scan<<<1, 1024>>>();
  k_scatter<<<(ET+255)/256, 256>>>(ei);
  k_sortseg<<<2500, 256>>>(ei);
  k_seqidx<<<BB, 256>>>(seq, len);
  cudaMemsetAsync(p_lstm, 0, (size_t)BB*TT*256*sizeof(float));

  // GAT layer 1
  k_attdot1<<<(NN*4+255)/256, 256>>>(g1as, g1ad);
  k_agg1<<<2500, 256>>>(g1b);

  // GAT layer 2
  k_hgemm<<<dim3(2, 157), 256>>>(p_z1h, p_z1l, p_w2h, p_w2l,
      nullptr, p_h2, NN, 128, 256, nullptr, nullptr, 0);
  k_attdot2<<<(NN+255)/256, 256>>>(g2as, g2ad);
  k_agg2<<<2500, 256>>>(g2b);

  // x-projections over valid rows (A gathered from z2 by node id, C scattered by (b,t))
  k_hgemm<<<dim3(8, 200), 256>>>(p_z2h, p_z2l, p_wih,             p_wih + 512*128,
      bf, p_xp,                      BB*TT, 512, 128, p_af, p_ci, 1);
  k_hgemm<<<dim3(8, 200), 256>>>(p_z2h, p_z2l, p_wih + 2*512*128, p_wih + 3*512*128,
      bb, p_xp + (size_t)BB*TT*512,  BB*TT, 512, 128, p_ab, p_ci, 1);

  // BiLSTM (length-sorted pairing via g_perm)
  k_lstm<<<dim3(64, 2), 512, lstm_smem>>>(whhf, whhb, len);

  // attention pooling + output heads
  k_attnpool<<<dim3(BB, 2), 256>>>(anw, anb, asw, asb, len);
  k_hgemm_fcn<<<313, 256>>>(p_cxh, p_cxl, fnW, fnb, out, BB, 20000, 256);
  k_gemm<<<dim3(1, 2), 256>>>(p_ctx + BB*256, fsW, fsb, out + (size_t)BB*20000, BB, 64, 256);
}

// round 14
// speedup vs baseline: 1.0203x; 1.0203x over previous
#include <cuda_runtime.h>
#include <cuda_bf16.h>
#include <cstdint>

typedef unsigned long long ull;
typedef __nv_bfloat16 bf16;

#define NN 20000
#define NE 320000
#define ET (NE+NN)
#define BB 128
#define TT 200

__device__ __forceinline__ ull fma2(ull a, ull b, ull c){
  ull d; asm("fma.rn.f32x2 %0, %1, %2, %3;" : "=l"(d) : "l"(a), "l"(b), "l"(c)); return d;
}
__device__ __forceinline__ float hsum2(ull v){
  float lo, hi; asm("mov.b64 {%0, %1}, %2;" : "=f"(lo), "=f"(hi) : "l"(v)); return lo + hi;
}
__device__ __forceinline__ float sigf(float x){ return 1.f/(1.f+__expf(-x)); }

__device__ __forceinline__ void bsplit(float x, bf16* h, bf16* l){
  bf16 hb = __float2bfloat16(x);
  *h = hb;
  *l = __float2bfloat16(x - __bfloat162float(hb));
}

#define MMA_BF16(C, A, B) \
  asm volatile("mma.sync.aligned.m16n8k16.row.col.f32.bf16.bf16.f32 " \
    "{%0,%1,%2,%3}, {%4,%5,%6,%7}, {%8,%9}, {%0,%1,%2,%3};" \
    : "+f"((C)[0]), "+f"((C)[1]), "+f"((C)[2]), "+f"((C)[3]) \
    : "r"((A)[0]), "r"((A)[1]), "r"((A)[2]), "r"((A)[3]), "r"((B)[0]), "r"((B)[1]))

__device__ __forceinline__ void ldsm_x4(uint32_t* r, const void* p){
  uint32_t a = (uint32_t)__cvta_generic_to_shared(p);
  asm volatile("ldmatrix.sync.aligned.m8n8.x4.shared.b16 {%0,%1,%2,%3}, [%4];"
    : "=r"(r[0]), "=r"(r[1]), "=r"(r[2]), "=r"(r[3]) : "r"(a));
}

// ---------------- scratch (device globals; no allocs) ----------------
__device__ float g_h1[NN*256];
__device__ float g_h2[NN*128];
__device__ float g_as1[NN*4];
__device__ float g_ad1[NN*4];
__device__ float g_as2[NN];
__device__ float g_ad2[NN];
__device__ int   g_cnt[NN];
__device__ int   g_fill[NN];
__device__ int   g_rowptr[NN+1];
__device__ int   g_srcs[ET];
__device__ float g_xproj[2][(size_t)BB*TT*512];
__device__ float g_lstm[BB*TT*256];
__device__ float g_ctx[2][BB*256];
__device__ int   g_aidxf[BB*TT];
__device__ int   g_aidxb[BB*TT];
__device__ int   g_cidx[BB*TT];
__device__ int   g_mc;
// bf16 split operand buffers
__device__ bf16 g_nfh[NN*144],  g_nfl[NN*144];
__device__ bf16 g_w1h[256*144], g_w1l[256*144];
__device__ bf16 g_z1h[NN*256],  g_z1l[NN*256];
__device__ bf16 g_w2h[128*256], g_w2l[128*256];
__device__ bf16 g_z2h[NN*128],  g_z2l[NN*128];
__device__ bf16 g_wih[2][2][512*128];
__device__ bf16 g_cxh[BB*256],  g_cxl[BB*256];

// ---------------- prep ----------------
__global__ void k_prep(const float* __restrict__ xc, const float* __restrict__ tf,
                       const float* __restrict__ emb,
                       const float* __restrict__ wihf, const float* __restrict__ wihb){
  int i = blockIdx.x*256 + threadIdx.x;
  if (i < NN*144){
    int r = i/144, c = i - r*144;
    float v = 0.f;
    if (c < 2)        v = xc[r*2 + c];
    else if (c < 130) v = emb[r*128 + (c-2)];
    else if (c < 134) v = tf[r*4 + (c-130)];
    bsplit(v, &g_nfh[i], &g_nfl[i]);
  }
  if (i < 512*128){
    bsplit(wihf[i], &g_wih[0][0][i], &g_wih[0][1][i]);
    bsplit(wihb[i], &g_wih[1][0][i], &g_wih[1][1][i]);
  }
}

// ---------------- transpose + bf16 split ----------------
__global__ void k_tsplit(const float* __restrict__ src, bf16* __restrict__ dh,
                         bf16* __restrict__ dl, int Ks, int Ns, int Kp){
  __shared__ float t[32][33];
  int n0 = blockIdx.x*32, k0 = blockIdx.y*32;
  int tx = threadIdx.x, ty = threadIdx.y;
  int k = k0 + ty, n = n0 + tx;
  t[ty][tx] = (k < Ks && n < Ns) ? src[(size_t)k*Ns + n] : 0.f;
  __syncthreads();
  int nn = n0 + ty, kk = k0 + tx;
  if (nn < Ns && kk < Kp){
    float v = t[tx][ty];
    bsplit(v, &dh[(size_t)nn*Kp + kk], &dl[(size_t)nn*Kp + kk]);
  }
}

// ---------------- compact valid (b,t) rows ----------------
__global__ void k_seqidx(const int* __restrict__ seq, const int* __restrict__ lengths){
  __shared__ int red[256];
  int b = blockIdx.x, tid = threadIdx.x;
  red[tid] = (tid < b) ? lengths[tid] : 0;
  __syncthreads();
  #pragma unroll
  for (int o = 128; o; o >>= 1){ if (tid < o) red[tid] += red[tid+o]; __syncthreads(); }
  int off = red[0];
  int len = lengths[b];
  for (int t = tid; t < len; t += 256){
    g_aidxf[off+t] = seq[b*TT + t];
    g_aidxb[off+t] = seq[b*TT + (len-1-t)];
    g_cidx[off+t]  = b*TT + t;
  }
  if (b == BB-1 && tid == 0) g_mc = off + len;
}

// ---------------- CSR build ----------------
__global__ void k_zero_cnt(){
  int i = blockIdx.x*256 + threadIdx.x;
  if (i < NN){ g_cnt[i] = 0; g_fill[i] = 0; }
}
__global__ void k_count(const int* __restrict__ ei){
  int e = blockIdx.x*256 + threadIdx.x;
  if (e >= ET) return;
  int d = (e < NE) ? ei[NE + e] : (e - NE);
  atomicAdd(&g_cnt[d], 1);
}
__global__ void k_scan(){
  __shared__ int ps[1024];
  int tid = threadIdx.x;
  int base = tid*20;
  int sum = 0;
  for (int j = 0; j < 20; j++){ int i = base + j; if (i < NN) sum += g_cnt[i]; }
  ps[tid] = sum;
  __syncthreads();
  for (int off = 1; off < 1024; off <<= 1){
    int v = (tid >= off) ? ps[tid-off] : 0;
    __syncthreads();
    ps[tid] += v;
    __syncthreads();
  }
  int run = ps[tid] - sum;
  for (int j = 0; j < 20; j++){ int i = base + j; if (i < NN){ g_rowptr[i] = run; run += g_cnt[i]; } }
  if (tid == 0) g_rowptr[NN] = ET;
}
__global__ void k_scatter(const int* __restrict__ ei){
  int e = blockIdx.x*256 + threadIdx.x;
  if (e >= ET) return;
  int d = (e < NE) ? ei[NE + e] : (e - NE);
  int p = atomicAdd(&g_fill[d], 1);
  g_srcs[g_rowptr[d] + p] = e;
}
__global__ void k_sortseg(const int* __restrict__ ei){
  __shared__ int buf[8][128];
  int wid = threadIdx.x >> 5, lane = threadIdx.x & 31;
  int n = blockIdx.x*8 + wid;
  if (n >= NN) return;
  int r0 = g_rowptr[n], r1 = g_rowptr[n+1], d = r1 - r0;
  if (d <= 128){
    for (int j = lane; j < d; j += 32) buf[wid][j] = g_srcs[r0 + j];
    __syncwarp();
    if (lane == 0){
      for (int a = 1; a < d; a++){
        int v = buf[wid][a]; int b = a - 1;
        while (b >= 0 && buf[wid][b] > v){ buf[wid][b+1] = buf[wid][b]; b--; }
        buf[wid][b+1] = v;
      }
    }
    __syncwarp();
    for (int j = lane; j < d; j += 32){
      int id = buf[wid][j];
      g_srcs[r0 + j] = (id < NE) ? ei[id] : (id - NE);
    }
  } else {
    for (int j = lane; j < d; j += 32){
      int id = g_srcs[r0 + j];
      g_srcs[r0 + j] = (id < NE) ? ei[id] : (id - NE);
    }
  }
}

// ---- bf16-split HMMA GEMM with ldmatrix fragment loads ----
__global__ void __launch_bounds__(256, 2)
k_hgemm(const bf16* __restrict__ Ah, const bf16* __restrict__ Al,
        const bf16* __restrict__ Bh, const bf16* __restrict__ Bl,
        const float* __restrict__ bias, float* __restrict__ C,
        int M, int Ntot, int K,
        const int* __restrict__ Aidx, const int* __restrict__ Cidx, int useMc){
  __shared__ bf16 sAh[128][24], sAl[128][24], sBh[64][24], sBl[64][24];
  int tid = threadIdx.x, warp = tid >> 5, lane = tid & 31;
  int Mr = useMc ? g_mc : M;
  int bm = blockIdx.y*128;
  if (bm >= Mr) return;
  int bn = blockIdx.x*64;
  int wm = (warp >> 1)*32, wn = (warp & 1)*32;

  float c[2][4][4];
  #pragma unroll
  for (int mi = 0; mi < 2; mi++)
    #pragma unroll
    for (int ni = 0; ni < 4; ni++)
      #pragma unroll
      for (int q = 0; q < 4; q++) c[mi][ni][q] = 0.f;

  int arow = tid >> 1, au = (tid & 1) << 3;
  int grA = bm + arow;
  const bf16* pAh = nullptr; const bf16* pAl = nullptr;
  if (grA < Mr){
    int src = Aidx ? Aidx[grA] : grA;
    pAh = Ah + (size_t)src*K;
    pAl = Al + (size_t)src*K;
  }
  int brow = (tid & 127) >> 1, bu = (tid & 1) << 3;
  bool bhi = tid < 128;
  int gnB = bn + brow;
  const bf16* pB = nullptr;
  if (gnB < Ntot) pB = (bhi ? Bh : Bl) + (size_t)gnB*K;

  int nk = K >> 4;
  uint4 zz = make_uint4(0,0,0,0);
  uint4 vAh = zz, vAl = zz, vB = zz;
  if (pAh){ vAh = *(const uint4*)(pAh + au); vAl = *(const uint4*)(pAl + au); }
  if (pB)  vB  = *(const uint4*)(pB + bu);
  *(uint4*)&sAh[arow][au] = vAh;
  *(uint4*)&sAl[arow][au] = vAl;
  if (bhi) *(uint4*)&sBh[brow][bu] = vB; else *(uint4*)&sBl[brow][bu] = vB;
  __syncthreads();

  int r = lane >> 2, kq = (lane & 3) << 1;
  int lq = lane & 7, ts = lane >> 3;
  int aro = lq + ((ts & 1) ? 8 : 0);       // A ldmatrix row offset within 16
  int aco = (ts & 2) ? 8 : 0;              // A ldmatrix col offset
  int bro = lq + ((ts & 2) ? 8 : 0);       // B ldmatrix row offset within 16
  int bco = (ts & 1) ? 8 : 0;              // B ldmatrix col offset
  for (int kc = 0; kc < nk; kc++){
    bool more = (kc + 1 < nk);
    if (more){
      int k0 = (kc + 1) << 4;
      vAh = zz; vAl = zz; vB = zz;
      if (pAh){ vAh = *(const uint4*)(pAh + k0 + au); vAl = *(const uint4*)(pAl + k0 + au); }
      if (pB)  vB  = *(const uint4*)(pB + k0 + bu);
    }
    uint32_t fah[2][4], fal[2][4], fbp[2][4];   // fbp[np] = {bh[2ni],bh[2ni]k8,bh[2ni+1],..} see below
    #pragma unroll
    for (int mi = 0; mi < 2; mi++){
      int rb = wm + mi*16 + aro;
      ldsm_x4(fah[mi], &sAh[rb][aco]);
      ldsm_x4(fal[mi], &sAl[rb][aco]);
    }
    uint32_t fbh[4][2], fbl[4][2];
    #pragma unroll
    for (int np = 0; np < 2; np++){
      int nb = wn + np*16 + bro;
      uint32_t th[4], tl[4];
      ldsm_x4(th, &sBh[nb][bco]);
      ldsm_x4(tl, &sBl[nb][bco]);
      fbh[np*2  ][0] = th[0]; fbh[np*2  ][1] = th[1];
      fbh[np*2+1][0] = th[2]; fbh[np*2+1][1] = th[3];
      fbl[np*2  ][0] = tl[0]; fbl[np*2  ][1] = tl[1];
      fbl[np*2+1][0] = tl[2]; fbl[np*2+1][1] = tl[3];
    }
    (void)fbp;
    #pragma unroll
    for (int mi = 0; mi < 2; mi++)
      #pragma unroll
      for (int ni = 0; ni < 4; ni++){
        MMA_BF16(c[mi][ni], fah[mi], fbh[ni]);
        MMA_BF16(c[mi][ni], fah[mi], fbl[ni]);
        MMA_BF16(c[mi][ni], fal[mi], fbh[ni]);
      }
    if (more){
      __syncthreads();
      *(uint4*)&sAh[arow][au] = vAh;
      *(uint4*)&sAl[arow][au] = vAl;
      if (bhi) *(uint4*)&sBh[brow][bu] = vB; else *(uint4*)&sBl[brow][bu] = vB;
      __syncthreads();
    }
  }

  #pragma unroll
  for (int mi = 0; mi < 2; mi++){
    #pragma unroll
    for (int ni = 0; ni < 4; ni++){
      int col = bn + wn + ni*8 + kq;
      if (col >= Ntot) continue;
      float bx = 0.f, by = 0.f;
      if (bias){ bx = bias[col]; by = bias[col+1]; }
      int row0 = bm + wm + mi*16 + r;
      if (row0 < Mr){
        int cr = Cidx ? Cidx[row0] : row0;
        float2 v = make_float2(c[mi][ni][0] + bx, c[mi][ni][1] + by);
        *(float2*)(C + (size_t)cr*Ntot + col) = v;
      }
      if (row0 + 8 < Mr){
        int cr = Cidx ? Cidx[row0+8] : row0+8;
        float2 v = make_float2(c[mi][ni][2] + bx, c[mi][ni][3] + by);
        *(float2*)(C + (size_t)cr*Ntot + col) = v;
      }
    }
  }
}

// ---- fc_node HMMA GEMM: B from f32 [K][N], split on the fly; ldmatrix loads ----
__global__ void __launch_bounds__(256, 2)
k_hgemm_fcn(const bf16* __restrict__ Ah, const bf16* __restrict__ Al,
            const float* __restrict__ Bf, const float* __restrict__ bias,
            float* __restrict__ C, int M, int Ntot, int K){
  __shared__ bf16 sAh[128][24], sAl[128][24], sBh[64][24], sBl[64][24];
  int tid = threadIdx.x, warp = tid >> 5, lane = tid & 31;
  int bm = 0;
  int bn = blockIdx.x*64;
  int wm = (warp >> 1)*32, wn = (warp & 1)*32;

  float c[2][4][4];
  #pragma unroll
  for (int mi = 0; mi < 2; mi++)
    #pragma unroll
    for (int ni = 0; ni < 4; ni++)
      #pragma unroll
      for (int q = 0; q < 4; q++) c[mi][ni][q] = 0.f;

  int arow = tid >> 1, au = (tid & 1) << 3;
  const bf16* pAh = Ah + (size_t)arow*K;
  const bf16* pAl = Al + (size_t)arow*K;
  int bk = tid >> 4, bn4 = (tid & 15) << 2;
  bool bok = (bn + bn4 < Ntot);

  int nk = K >> 4;
  uint4 vAh, vAl;
  float4 vB = make_float4(0.f,0.f,0.f,0.f);
  vAh = *(const uint4*)(pAh + au);
  vAl = *(const uint4*)(pAl + au);
  if (bok) vB = *(const float4*)(Bf + (size_t)bk*Ntot + bn + bn4);
  *(uint4*)&sAh[arow][au] = vAh;
  *(uint4*)&sAl[arow][au] = vAl;
  {
    float bvals[4] = {vB.x, vB.y, vB.z, vB.w};
    #pragma unroll
    for (int i = 0; i < 4; i++)
      bsplit(bvals[i], &sBh[bn4 + i][bk], &sBl[bn4 + i][bk]);
  }
  __syncthreads();

  int r = lane >> 2, kq = (lane & 3) << 1;
  int lq = lane & 7, ts = lane >> 3;
  int aro = lq + ((ts & 1) ? 8 : 0);
  int aco = (ts & 2) ? 8 : 0;
  int bro = lq + ((ts & 2) ? 8 : 0);
  int bco = (ts & 1) ? 8 : 0;
  for (int kc = 0; kc < nk; kc++){
    bool more = (kc + 1 < nk);
    if (more){
      int k0 = (kc + 1) << 4;
      vAh = *(const uint4*)(pAh + k0 + au);
      vAl = *(const uint4*)(pAl + k0 + au);
      vB = make_float4(0.f,0.f,0.f,0.f);
      if (bok) vB = *(const float4*)(Bf + (size_t)(k0 + bk)*Ntot + bn + bn4);
    }
    uint32_t fah[2][4], fal[2][4], fbh[4][2], fbl[4][2];
    #pragma unroll
    for (int mi = 0; mi < 2; mi++){
      int rb = wm + mi*16 + aro;
      ldsm_x4(fah[mi], &sAh[rb][aco]);
      ldsm_x4(fal[mi], &sAl[rb][aco]);
    }
    #pragma unroll
    for (int np = 0; np < 2; np++){
      int nb = wn + np*16 + bro;
      uint32_t th[4], tl[4];
      ldsm_x4(th, &sBh[nb][bco]);
      ldsm_x4(tl, &sBl[nb][bco]);
      fbh[np*2  ][0] = th[0]; fbh[np*2  ][1] = th[1];
      fbh[np*2+1][0] = th[2]; fbh[np*2+1][1] = th[3];
      fbl[np*2  ][0] = tl[0]; fbl[np*2  ][1] = tl[1];
      fbl[np*2+1][0] = tl[2]; fbl[np*2+1][1] = tl[3];
    }
    #pragma unroll
    for (int mi = 0; mi < 2; mi++)
      #pragma unroll
      for (int ni = 0; ni < 4; ni++){
        MMA_BF16(c[mi][ni], fah[mi], fbh[ni]);
        MMA_BF16(c[mi][ni], fah[mi], fbl[ni]);
        MMA_BF16(c[mi][ni], fal[mi], fbh[ni]);
      }
    if (more){
      __syncthreads();
      *(uint4*)&sAh[arow][au] = vAh;
      *(uint4*)&sAl[arow][au] = vAl;
      float bvals[4] = {vB.x, vB.y, vB.z, vB.w};
      #pragma unroll
      for (int i = 0; i < 4; i++)
        bsplit(bvals[i], &sBh[bn4 + i][bk], &sBl[bn4 + i][bk]);
      __syncthreads();
    }
  }

  #pragma unroll
  for (int mi = 0; mi < 2; mi++){
    #pragma unroll
    for (int ni = 0; ni < 4; ni++){
      int col = bn + wn + ni*8 + kq;
      if (col >= Ntot) continue;
      float bx = bias[col], by = bias[col+1];
      int row0 = bm + wm + mi*16 + r;
      float2 v0 = make_float2(c[mi][ni][0] + bx, c[mi][ni][1] + by);
      *(float2*)(C + (size_t)row0*Ntot + col) = v0;
      float2 v1 = make_float2(c[mi][ni][2] + bx, c[mi][ni][3] + by);
      *(float2*)(C + (size_t)(row0+8)*Ntot + col) = v1;
    }
  }
}

// ---------------- scalar SGEMM (fc_sp only) ----------------
__global__ void k_gemm(const float* __restrict__ A, const float* __restrict__ B,
                       const float* __restrict__ bias, float* __restrict__ C,
                       int M, int N, int K){
  __shared__ float As[16][64];
  __shared__ float Bs[16][64];
  int bn = blockIdx.x*64, bm = blockIdx.y*64;
  int tid = threadIdx.x;
  int tx = tid & 15, ty = tid >> 4;
  float acc[4][4];
  #pragma unroll
  for (int i = 0; i < 4; i++)
    #pragma unroll
    for (int j = 0; j < 4; j++) acc[i][j] = 0.f;
  int ar = tid >> 2, ak = (tid & 3) << 2;
  int bk = tid >> 4, bn2 = (tid & 15) << 2;
  for (int k0 = 0; k0 < K; k0 += 16){
    float4 av = make_float4(0.f,0.f,0.f,0.f);
    if (bm + ar < M) av = *(const float4*)(A + (size_t)(bm + ar)*K + k0 + ak);
    As[ak  ][ar] = av.x; As[ak+1][ar] = av.y; As[ak+2][ar] = av.z; As[ak+3][ar] = av.w;
    float4 bv = make_float4(0.f,0.f,0.f,0.f);
    if (bn + bn2 < N) bv = *(const float4*)(B + (size_t)(k0 + bk)*N + bn + bn2);
    *(float4*)&Bs[bk][bn2] = bv;
    __syncthreads();
    #pragma unroll
    for (int kk = 0; kk < 16; kk++){
      float4 ra = *(const float4*)&As[kk][ty << 2];
      float4 rb = *(const float4*)&Bs[kk][tx << 2];
      acc[0][0] += ra.x*rb.x; acc[0][1] += ra.x*rb.y; acc[0][2] += ra.x*rb.z; acc[0][3] += ra.x*rb.w;
      acc[1][0] += ra.y*rb.x; acc[1][1] += ra.y*rb.y; acc[1][2] += ra.y*rb.z; acc[1][3] += ra.y*rb.w;
      acc[2][0] += ra.z*rb.x; acc[2][1] += ra.z*rb.y; acc[2][2] += ra.z*rb.z; acc[2][3] += ra.z*rb.w;
      acc[3][0] += ra.w*rb.x; acc[3][1] += ra.w*rb.y; acc[3][2] += ra.w*rb.z; acc[3][3] += ra.w*rb.w;
    }
    __syncthreads();
  }
  #pragma unroll
  for (int i = 0; i < 4; i++){
    int row = bm + (ty << 2) + i;
    if (row >= M) continue;
    #pragma unroll
    for (int j = 0; j < 4; j++){
      int col = bn + (tx << 2) + j;
      if (col >= N) continue;
      float v = acc[i][j];
      if (bias) v += bias[col];
      C[(size_t)row*N + col] = v;
    }
  }
}

// ---------------- attention dots ----------------
__global__ void k_attdot1(const float* __restrict__ aw_s, const float* __restrict__ aw_d){
  int i = blockIdx.x*256 + threadIdx.x;
  if (i >= NN*4) return;
  int n = i >> 2, h = i & 3;
  const float4* hp = (const float4*)(g_h1 + n*256 + h*64);
  const float4* sw = (const float4*)(aw_s + h*64);
  const float4* dw = (const float4*)(aw_d + h*64);
  float s = 0.f, d = 0.f;
  #pragma unroll
  for (int j = 0; j < 16; j++){
    float4 x = hp[j], a = sw[j], b = dw[j];
    s += x.x*a.x + x.y*a.y + x.z*a.z + x.w*a.w;
    d += x.x*b.x + x.y*b.y + x.z*b.z + x.w*b.w;
  }
  g_as1[i] = s; g_ad1[i] = d;
}
__global__ void k_attdot2(const float* __restrict__ aw_s, const float* __restrict__ aw_d){
  int n = blockIdx.x*256 + threadIdx.x;
  if (n >= NN) return;
  const float4* hp = (const float4*)(g_h2 + n*128);
  const float4* sw = (const float4*)aw_s;
  const float4* dw = (const float4*)aw_d;
  float s = 0.f, d = 0.f;
  #pragma unroll
  for (int j = 0; j < 32; j++){
    float4 x = hp[j], a = sw[j], b = dw[j];
    s += x.x*a.x + x.y*a.y + x.z*a.z + x.w*a.w;
    d += x.x*b.x + x.y*b.y + x.z*b.z + x.w*b.w;
  }
  g_as2[n] = s; g_ad2[n] = d;
}

// ---------------- edge softmax + aggregation, layer 1 -> z1 bf16 split ----------------
__global__ void k_agg1(const float* __restrict__ bias){
  int wid = threadIdx.x >> 5, lane = threadIdx.x & 31;
  int n = blockIdx.x*8 + wid;
  int r0 = g_rowptr[n], r1 = g_rowptr[n+1];
  float4 ad = *(const float4*)(g_ad1 + n*4);
  float m0 = -1e30f, m1 = -1e30f, m2 = -1e30f, m3 = -1e30f;
  for (int e = r0 + lane; e < r1; e += 32){
    int s = g_srcs[e];
    float4 as = *(const float4*)(g_as1 + s*4);
    float v0 = as.x + ad.x; v0 = v0 > 0.f ? v0 : 0.2f*v0;
    float v1 = as.y + ad.y; v1 = v1 > 0.f ? v1 : 0.2f*v1;
    float v2 = as.z + ad.z; v2 = v2 > 0.f ? v2 : 0.2f*v2;
    float v3 = as.w + ad.w; v3 = v3 > 0.f ? v3 : 0.2f*v3;
    m0 = fmaxf(m0, v0); m1 = fmaxf(m1, v1); m2 = fmaxf(m2, v2); m3 = fmaxf(m3, v3);
  }
  #pragma unroll
  for (int o = 16; o; o >>= 1){
    m0 = fmaxf(m0, __shfl_xor_sync(0xffffffffu, m0, o));
    m1 = fmaxf(m1, __shfl_xor_sync(0xffffffffu, m1, o));
    m2 = fmaxf(m2, __shfl_xor_sync(0xffffffffu, m2, o));
    m3 = fmaxf(m3, __shfl_xor_sync(0xffffffffu, m3, o));
  }
  float s0 = 0.f, s1 = 0.f, s2 = 0.f, s3 = 0.f;
  for (int e = r0 + lane; e < r1; e += 32){
    int s = g_srcs[e];
    float4 as = *(const float4*)(g_as1 + s*4);
    float v0 = as.x + ad.x; v0 = v0 > 0.f ? v0 : 0.2f*v0;
    float v1 = as.y + ad.y; v1 = v1 > 0.f ? v1 : 0.2f*v1;
    float v2 = as.z + ad.z; v2 = v2 > 0.f ? v2 : 0.2f*v2;
    float v3 = as.w + ad.w; v3 = v3 > 0.f ? v3 : 0.2f*v3;
    s0 += __expf(v0 - m0); s1 += __expf(v1 - m1);
    s2 += __expf(v2 - m2); s3 += __expf(v3 - m3);
  }
  #pragma unroll
  for (int o = 16; o; o >>= 1){
    s0 += __shfl_xor_sync(0xffffffffu, s0, o);
    s1 += __shfl_xor_sync(0xffffffffu, s1, o);
    s2 += __shfl_xor_sync(0xffffffffu, s2, o);
    s3 += __shfl_xor_sync(0xffffffffu, s3, o);
  }
  int hsel = lane >> 3;
  float mh  = hsel == 0 ? m0 : hsel == 1 ? m1 : hsel == 2 ? m2 : m3;
  float inv = 1.f / (hsel == 0 ? s0 : hsel == 1 ? s1 : hsel == 2 ? s2 : s3);
  float adh = hsel == 0 ? ad.x : hsel == 1 ? ad.y : hsel == 2 ? ad.z : ad.w;
  float a0=0,a1=0,a2=0,a3=0,a4=0,a5=0,a6=0,a7=0;
  for (int e = r0; e < r1; e++){
    int s = g_srcs[e];
    float v = g_as1[s*4 + hsel] + adh; v = v > 0.f ? v : 0.2f*v;
    float alpha = __expf(v - mh) * inv;
    const float4* xp = (const float4*)(g_h1 + s*256 + lane*8);
    float4 x0 = xp[0], x1 = xp[1];
    a0 += alpha*x0.x; a1 += alpha*x0.y; a2 += alpha*x0.z; a3 += alpha*x0.w;
    a4 += alpha*x1.x; a5 += alpha*x1.y; a6 += alpha*x1.z; a7 += alpha*x1.w;
  }
  int cb = lane*8;
  float r[8] = {a0,a1,a2,a3,a4,a5,a6,a7};
  #pragma unroll
  for (int i = 0; i < 8; i++){
    float o = r[i] + bias[cb + i];
    o = o > 0.f ? o : expm1f(o);                           // ELU
    bsplit(o, &g_z1h[n*256 + cb + i], &g_z1l[n*256 + cb + i]);
  }
}

// ---------------- edge softmax + aggregation, layer 2 -> z2 bf16 split ----------------
__global__ void k_agg2(const float* __restrict__ bias){
  int wid = threadIdx.x >> 5, lane = threadIdx.x & 31;
  int n = blockIdx.x*8 + wid;
  int r0 = g_rowptr[n], r1 = g_rowptr[n+1];
  float ad = g_ad2[n];
  float m = -1e30f;
  for (int e = r0 + lane; e < r1; e += 32){
    float v = g_as2[g_srcs[e]] + ad; v = v > 0.f ? v : 0.2f*v;
    m = fmaxf(m, v);
  }
  #pragma unroll
  for (int o = 16; o; o >>= 1) m = fmaxf(m, __shfl_xor_sync(0xffffffffu, m, o));
  float ssum = 0.f;
  for (int e = r0 + lane; e < r1; e += 32){
    float v = g_as2[g_srcs[e]] + ad; v = v > 0.f ? v : 0.2f*v;
    ssum += __expf(v - m);
  }
  #pragma unroll
  for (int o = 16; o; o >>= 1) ssum += __shfl_xor_sync(0xffffffffu, ssum, o);
  float inv = 1.f / ssum;
  float a0=0,a1=0,a2=0,a3=0;
  for (int e = r0; e < r1; e++){
    int s = g_srcs[e];
    float v = g_as2[s] + ad; v = v > 0.f ? v : 0.2f*v;
    float alpha = __expf(v - m) * inv;
    float4 x = *(const float4*)(g_h2 + s*128 + lane*4);
    a0 += alpha*x.x; a1 += alpha*x.y; a2 += alpha*x.z; a3 += alpha*x.w;
  }
  int cb = lane*4;
  float rr[4] = {a0 + bias[cb], a1 + bias[cb+1], a2 + bias[cb+2], a3 + bias[cb+3]};
  #pragma unroll
  for (int i = 0; i < 4; i++)
    bsplit(rr[i], &g_z2h[n*128 + cb + i], &g_z2l[n*128 + cb + i]);
}

// ---------------- BiLSTM recurrence (round-12 proven version) ----------------
__global__ void __launch_bounds__(512, 1)
k_lstm(const float* __restrict__ whhf, const float* __restrict__ whhb,
       const int* __restrict__ lengths){
  extern __shared__ char smraw[];
  ull*   ws  = (ull*)smraw;
  float* hsm = (float*)(ws + 512*33);
  float* gsm = hsm + 256;
  int g   = threadIdx.x;
  int dir = blockIdx.y;
  int b0  = blockIdx.x*2;
  const float* whh = dir ? whhb : whhf;
  const ull* wrow = (const ull*)(whh + g*128);
  ull wreg[32];
  #pragma unroll
  for (int j = 0; j < 32; j++) wreg[j] = wrow[j];
  #pragma unroll
  for (int j = 0; j < 32; j++) ws[g*33 + j] = wrow[32 + j];
  if (g < 256) hsm[g] = 0.f;
  float cc = 0.f;
  int len0 = lengths[b0], len1 = lengths[b0+1];
  int Tn = len0 > len1 ? len0 : len1;
  const float* x0p = g_xproj[dir] + (size_t)b0*TT*512;
  const float* x1p = x0p + (size_t)TT*512;
  __syncthreads();
  for (int t = 0; t < Tn; t++){
    float xv0 = x0p[t*512 + g];
    float xv1 = x1p[t*512 + g];
    ull a0 = 0ULL, a1 = 0ULL;
    const ull* h0p = (const ull*)hsm;
    const ull* h1p = (const ull*)(hsm + 128);
    #pragma unroll
    for (int j = 0; j < 32; j++){
      ull w = wreg[j];
      a0 = fma2(w, h0p[j], a0);
      a1 = fma2(w, h1p[j], a1);
    }
    #pragma unroll
    for (int j = 0; j < 32; j++){
      ull w = ws[g*33 + j];
      a0 = fma2(w, h0p[32 + j], a0);
      a1 = fma2(w, h1p[32 + j], a1);
    }
    gsm[g]       = hsum2(a0) + xv0;
    gsm[512 + g] = hsum2(a1) + xv1;
    __syncthreads();
    if (g < 256){
      int b = g >> 7, j = g & 127;
      const float* gb = gsm + b*512;
      float gi = gb[j], gf = gb[128 + j], gg = gb[256 + j], go = gb[384 + j];
      cc = sigf(gf)*cc + sigf(gi)*tanhf(gg);
      float h = sigf(go)*tanhf(cc);
      hsm[b*128 + j] = h;
      int L = b ? len1 : len0;
      if (dir == 0){
        if (t < L) g_lstm[((size_t)(b0 + b)*TT + t)*256 + j] = h;
      } else {
        if (t < L) g_lstm[((size_t)(b0 + b)*TT + (L - 1 - t))*256 + 128 + j] = h;
      }
    }
    __syncthreads();
  }
}

// ---------------- masked attention pooling ----------------
__global__ void k_attnpool(const float* __restrict__ wn, const float* __restrict__ bn,
                           const float* __restrict__ wsp, const float* __restrict__ bsp,
                           const int* __restrict__ lengths){
  __shared__ float sc[256];
  __shared__ float red[256];
  int b = blockIdx.x, p = blockIdx.y;
  const float* w = p ? wsp : wn;
  float bias = p ? bsp[0] : bn[0];
  int tid = threadIdx.x;
  int len = lengths[b];
  float sv = -1e30f;
  if (tid < TT && tid < len){
    const float4* row = (const float4*)(g_lstm + ((size_t)b*TT + tid)*256);
    const float4* wv = (const float4*)w;
    float s = 0.f;
    #pragma unroll
    for (int j = 0; j < 64; j++){
      float4 x = row[j], y = wv[j];
      s += x.x*y.x + x.y*y.y + x.z*y.z + x.w*y.w;
    }
    sv = s + bias;
  }
  red[tid] = sv;
  __syncthreads();
  #pragma unroll
  for (int o = 128; o; o >>= 1){ if (tid < o) red[tid] = fmaxf(red[tid], red[tid+o]); __syncthreads(); }
  float m = red[0];
  __syncthreads();
  float e = (sv <= -1e29f) ? 0.f : __expf(sv - m);
  sc[tid] = e; red[tid] = e;
  __syncthreads();
  #pragma unroll
  for (int o = 128; o; o >>= 1){ if (tid < o) red[tid] += red[tid+o]; __syncthreads(); }
  float inv = 1.f / red[0];
  float acc = 0.f;
  for (int t = 0; t < TT; t++)
    acc += sc[t] * g_lstm[((size_t)b*TT + t)*256 + tid];
  float v = acc * inv;
  g_ctx[p][b*256 + tid] = v;
  if (p == 0) bsplit(v, &g_cxh[b*256 + tid], &g_cxl[b*256 + tid]);
}

// ---------------- launch ----------------
extern "C" void kernel_launch(void* const* d_in, const int* in_sizes, int n_in,
                              void* d_out, int out_size){
  const float* xc   = (const float*)d_in[0];
  const float* tf   = (const float*)d_in[1];
  const float* emb  = (const float*)d_in[2];
  const float* g1W  = (const float*)d_in[3];
  const float* g1as = (const float*)d_in[4];
  const float* g1ad = (const float*)d_in[5];
  const float* g1b  = (const float*)d_in[6];
  const float* g2W  = (const float*)d_in[7];
  const float* g2as = (const float*)d_in[8];
  const float* g2ad = (const float*)d_in[9];
  const float* g2b  = (const float*)d_in[10];
  const float* wihf = (const float*)d_in[11];
  const float* whhf = (const float*)d_in[12];
  const float* bf   = (const float*)d_in[13];
  const float* wihb = (const float*)d_in[14];
  const float* whhb = (const float*)d_in[15];
  const float* bb   = (const float*)d_in[16];
  const float* anw  = (const float*)d_in[17];
  const float* anb  = (const float*)d_in[18];
  const float* asw  = (const float*)d_in[19];
  const float* asb  = (const float*)d_in[20];
  const float* fnW  = (const float*)d_in[21];
  const float* fnb  = (const float*)d_in[22];
  const float* fsW  = (const float*)d_in[23];
  const float* fsb  = (const float*)d_in[24];
  const int*   ei   = (const int*)d_in[25];
  const int*   seq  = (const int*)d_in[26];
  const int*   len  = (const int*)d_in[27];
  float* out = (float*)d_out;

  float *p_h1, *p_h2, *p_xp, *p_ctx, *p_lstm;
  int *p_af, *p_ab, *p_ci;
  bf16 *p_nfh, *p_nfl, *p_w1h, *p_w1l, *p_z1h, *p_z1l, *p_w2h, *p_w2l;
  bf16 *p_z2h, *p_z2l, *p_wih, *p_cxh, *p_cxl;
  cudaGetSymbolAddress((void**)&p_h1,  g_h1);
  cudaGetSymbolAddress((void**)&p_h2,  g_h2);
  cudaGetSymbolAddress((void**)&p_xp,  g_xproj);
  cudaGetSymbolAddress((void**)&p_ctx, g_ctx);
  cudaGetSymbolAddress((void**)&p_lstm, g_lstm);
  cudaGetSymbolAddress((void**)&p_af,  g_aidxf);
  cudaGetSymbolAddress((void**)&p_ab,  g_aidxb);
  cudaGetSymbolAddress((void**)&p_ci,  g_cidx);
  cudaGetSymbolAddress((void**)&p_nfh, g_nfh);
  cudaGetSymbolAddress((void**)&p_nfl, g_nfl);
  cudaGetSymbolAddress((void**)&p_w1h, g_w1h);
  cudaGetSymbolAddress((void**)&p_w1l, g_w1l);
  cudaGetSymbolAddress((void**)&p_z1h, g_z1h);
  cudaGetSymbolAddress((void**)&p_z1l, g_z1l);
  cudaGetSymbolAddress((void**)&p_w2h, g_w2h);
  cudaGetSymbolAddress((void**)&p_w2l, g_w2l);
  cudaGetSymbolAddress((void**)&p_z2h, g_z2h);
  cudaGetSymbolAddress((void**)&p_z2l, g_z2l);
  cudaGetSymbolAddress((void**)&p_wih, g_wih);
  cudaGetSymbolAddress((void**)&p_cxh, g_cxh);
  cudaGetSymbolAddress((void**)&p_cxl, g_cxl);

  int lstm_smem = 512*33*8 + 256*4 + 1024*4;
  cudaFuncSetAttribute(k_lstm, cudaFuncAttributeMaxDynamicSharedMemorySize, lstm_smem);

  // index 3 (overall ncu launch #5) = GAT1 HMMA GEMM
  k_prep<<<11250, 256>>>(xc, tf, emb, wihf, wihb);                            // 0
  k_tsplit<<<dim3(8, 5),  dim3(32,32)>>>(g1W, p_w1h, p_w1l, 134, 256, 144);   // 1
  k_tsplit<<<dim3(4, 8),  dim3(32,32)>>>(g2W, p_w2h, p_w2l, 256, 128, 256);   // 2
  k_hgemm<<<dim3(4, 157), 256>>>(p_nfh, p_nfl, p_w1h, p_w1l,
      nullptr, p_h1, NN, 256, 144, nullptr, nullptr, 0);                      // 3 <- profiled
  k_zero_cnt<<<(NN+255)/256, 256>>>();
  k_count<<<(ET+255)/256, 256>>>(ei);
  k_scan<<<1, 1024>>>();
  k_scatter<<<(ET+255)/256, 256>>>(ei);
  k_sortseg<<<2500, 256>>>(ei);
  k_seqidx<<<BB, 256>>>(seq, len);
  cudaMemsetAsync(p_lstm, 0, (size_t)BB*TT*256*sizeof(float));

  // GAT layer 1
  k_attdot1<<<(NN*4+255)/256, 256>>>(g1as, g1ad);
  k_agg1<<<2500, 256>>>(g1b);

  // GAT layer 2
  k_hgemm<<<dim3(2, 157), 256>>>(p_z1h, p_z1l, p_w2h, p_w2l,
      nullptr, p_h2, NN, 128, 256, nullptr, nullptr, 0);
  k_attdot2<<<(NN+255)/256, 256>>>(g2as, g2ad);
  k_agg2<<<2500, 256>>>(g2b);

  // x-projections over valid rows (A gathered from z2 by node id, C scattered by (b,t))
  k_hgemm<<<dim3(8, 200), 256>>>(p_z2h, p_z2l, p_wih,             p_wih + 512*128,
      bf, p_xp,                      BB*TT, 512, 128, p_af, p_ci, 1);
  k_hgemm<<<dim3(8, 200), 256>>>(p_z2h, p_z2l, p_wih + 2*512*128, p_wih + 3*512*128,
      bb, p_xp + (size_t)BB*TT*512,  BB*TT, 512, 128, p_ab, p_ci, 1);

  // BiLSTM
  k_lstm<<<dim3(64, 2), 512, lstm_smem>>>(whhf, whhb, len);

  // attention pooling + output heads
  k_attnpool<<<dim3(BB, 2), 256>>>(anw, anb, asw, asb, len);
  k_hgemm_fcn<<<313, 256>>>(p_cxh, p_cxl, fnW, fnb, out, BB, 20000, 256);
  k_gemm<<<dim3(1, 2), 256>>>(p_ctx + BB*256, fsW, fsb, out + (size_t)BB*20000, BB, 64, 256);
}

// round 15
// speedup vs baseline: 1.0487x; 1.0278x over previous
#include <cuda_runtime.h>
#include <cuda_bf16.h>
#include <cstdint>

typedef unsigned long long ull;
typedef __nv_bfloat16 bf16;

#define NN 20000
#define NE 320000
#define ET (NE+NN)
#define BB 128
#define TT 200

__device__ __forceinline__ ull fma2(ull a, ull b, ull c){
  ull d; asm("fma.rn.f32x2 %0, %1, %2, %3;" : "=l"(d) : "l"(a), "l"(b), "l"(c)); return d;
}
__device__ __forceinline__ float hsum2(ull v){
  float lo, hi; asm("mov.b64 {%0, %1}, %2;" : "=f"(lo), "=f"(hi) : "l"(v)); return lo + hi;
}
__device__ __forceinline__ float sigf(float x){ return 1.f/(1.f+__expf(-x)); }

__device__ __forceinline__ void bsplit(float x, bf16* h, bf16* l){
  bf16 hb = __float2bfloat16(x);
  *h = hb;
  *l = __float2bfloat16(x - __bfloat162float(hb));
}

#define MMA_BF16(C, A, B) \
  asm volatile("mma.sync.aligned.m16n8k16.row.col.f32.bf16.bf16.f32 " \
    "{%0,%1,%2,%3}, {%4,%5,%6,%7}, {%8,%9}, {%0,%1,%2,%3};" \
    : "+f"((C)[0]), "+f"((C)[1]), "+f"((C)[2]), "+f"((C)[3]) \
    : "r"((A)[0]), "r"((A)[1]), "r"((A)[2]), "r"((A)[3]), "r"((B)[0]), "r"((B)[1]))

__device__ __forceinline__ void ldsm_x4(uint32_t* r, const void* p){
  uint32_t a = (uint32_t)__cvta_generic_to_shared(p);
  asm volatile("ldmatrix.sync.aligned.m8n8.x4.shared.b16 {%0,%1,%2,%3}, [%4];"
    : "=r"(r[0]), "=r"(r[1]), "=r"(r[2]), "=r"(r[3]) : "r"(a));
}

// ---------------- scratch (device globals; no allocs) ----------------
__device__ float g_h1[NN*256];
__device__ float g_h2[NN*128];
__device__ float g_as1[NN*4];
__device__ float g_ad1[NN*4];
__device__ float g_as2[NN];
__device__ float g_ad2[NN];
__device__ int   g_cnt[NN];
__device__ int   g_fill[NN];
__device__ int   g_rowptr[NN+1];
__device__ int   g_srcs[ET];
__device__ float g_xproj[2][(size_t)BB*TT*512];
__device__ float g_lstm[BB*TT*256];
__device__ float g_ctx[2][BB*256];
__device__ int   g_aidxf[BB*TT];
__device__ int   g_aidxb[BB*TT];
__device__ int   g_cidx[BB*TT];
__device__ int   g_mc;
// bf16 split operand buffers
__device__ bf16 g_nfh[NN*144],  g_nfl[NN*144];
__device__ bf16 g_w1h[256*144], g_w1l[256*144];
__device__ bf16 g_z1h[NN*256],  g_z1l[NN*256];
__device__ bf16 g_w2h[128*256], g_w2l[128*256];
__device__ bf16 g_z2h[NN*128],  g_z2l[NN*128];
__device__ bf16 g_wih[2][2][512*128];
__device__ bf16 g_cxh[BB*256],  g_cxl[BB*256];

// ---------------- prep ----------------
__global__ void k_prep(const float* __restrict__ xc, const float* __restrict__ tf,
                       const float* __restrict__ emb,
                       const float* __restrict__ wihf, const float* __restrict__ wihb){
  int i = blockIdx.x*256 + threadIdx.x;
  if (i < NN*144){
    int r = i/144, c = i - r*144;
    float v = 0.f;
    if (c < 2)        v = xc[r*2 + c];
    else if (c < 130) v = emb[r*128 + (c-2)];
    else if (c < 134) v = tf[r*4 + (c-130)];
    bsplit(v, &g_nfh[i], &g_nfl[i]);
  }
  if (i < 512*128){
    bsplit(wihf[i], &g_wih[0][0][i], &g_wih[0][1][i]);
    bsplit(wihb[i], &g_wih[1][0][i], &g_wih[1][1][i]);
  }
}

// ---------------- transpose + bf16 split ----------------
__global__ void k_tsplit(const float* __restrict__ src, bf16* __restrict__ dh,
                         bf16* __restrict__ dl, int Ks, int Ns, int Kp){
  __shared__ float t[32][33];
  int n0 = blockIdx.x*32, k0 = blockIdx.y*32;
  int tx = threadIdx.x, ty = threadIdx.y;
  int k = k0 + ty, n = n0 + tx;
  t[ty][tx] = (k < Ks && n < Ns) ? src[(size_t)k*Ns + n] : 0.f;
  __syncthreads();
  int nn = n0 + ty, kk = k0 + tx;
  if (nn < Ns && kk < Kp){
    float v = t[tx][ty];
    bsplit(v, &dh[(size_t)nn*Kp + kk], &dl[(size_t)nn*Kp + kk]);
  }
}

// ---------------- compact valid (b,t) rows ----------------
__global__ void k_seqidx(const int* __restrict__ seq, const int* __restrict__ lengths){
  __shared__ int red[256];
  int b = blockIdx.x, tid = threadIdx.x;
  red[tid] = (tid < b) ? lengths[tid] : 0;
  __syncthreads();
  #pragma unroll
  for (int o = 128; o; o >>= 1){ if (tid < o) red[tid] += red[tid+o]; __syncthreads(); }
  int off = red[0];
  int len = lengths[b];
  for (int t = tid; t < len; t += 256){
    g_aidxf[off+t] = seq[b*TT + t];
    g_aidxb[off+t] = seq[b*TT + (len-1-t)];
    g_cidx[off+t]  = b*TT + t;
  }
  if (b == BB-1 && tid == 0) g_mc = off + len;
}

// ---------------- CSR build ----------------
__global__ void k_zero_cnt(){
  int i = blockIdx.x*256 + threadIdx.x;
  if (i < NN){ g_cnt[i] = 0; g_fill[i] = 0; }
}
__global__ void k_count(const int* __restrict__ ei){
  int e = blockIdx.x*256 + threadIdx.x;
  if (e >= ET) return;
  int d = (e < NE) ? ei[NE + e] : (e - NE);
  atomicAdd(&g_cnt[d], 1);
}
__global__ void k_scan(){
  __shared__ int ps[1024];
  int tid = threadIdx.x;
  int base = tid*20;
  int sum = 0;
  for (int j = 0; j < 20; j++){ int i = base + j; if (i < NN) sum += g_cnt[i]; }
  ps[tid] = sum;
  __syncthreads();
  for (int off = 1; off < 1024; off <<= 1){
    int v = (tid >= off) ? ps[tid-off] : 0;
    __syncthreads();
    ps[tid] += v;
    __syncthreads();
  }
  int run = ps[tid] - sum;
  for (int j = 0; j < 20; j++){ int i = base + j; if (i < NN){ g_rowptr[i] = run; run += g_cnt[i]; } }
  if (tid == 0) g_rowptr[NN] = ET;
}
__global__ void k_scatter(const int* __restrict__ ei){
  int e = blockIdx.x*256 + threadIdx.x;
  if (e >= ET) return;
  int d = (e < NE) ? ei[NE + e] : (e - NE);
  int p = atomicAdd(&g_fill[d], 1);
  g_srcs[g_rowptr[d] + p] = e;
}
__global__ void k_sortseg(const int* __restrict__ ei){
  __shared__ int buf[8][128];
  int wid = threadIdx.x >> 5, lane = threadIdx.x & 31;
  int n = blockIdx.x*8 + wid;
  if (n >= NN) return;
  int r0 = g_rowptr[n], r1 = g_rowptr[n+1], d = r1 - r0;
  if (d <= 128){
    for (int j = lane; j < d; j += 32) buf[wid][j] = g_srcs[r0 + j];
    __syncwarp();
    if (lane == 0){
      for (int a = 1; a < d; a++){
        int v = buf[wid][a]; int b = a - 1;
        while (b >= 0 && buf[wid][b] > v){ buf[wid][b+1] = buf[wid][b]; b--; }
        buf[wid][b+1] = v;
      }
    }
    __syncwarp();
    for (int j = lane; j < d; j += 32){
      int id = buf[wid][j];
      g_srcs[r0 + j] = (id < NE) ? ei[id] : (id - NE);
    }
  } else {
    for (int j = lane; j < d; j += 32){
      int id = g_srcs[r0 + j];
      g_srcs[r0 + j] = (id < NE) ? ei[id] : (id - NE);
    }
  }
}

// ---- bf16-split HMMA GEMM with ldmatrix fragment loads ----
__global__ void __launch_bounds__(256, 2)
k_hgemm(const bf16* __restrict__ Ah, const bf16* __restrict__ Al,
        const bf16* __restrict__ Bh, const bf16* __restrict__ Bl,
        const float* __restrict__ bias, float* __restrict__ C,
        int M, int Ntot, int K,
        const int* __restrict__ Aidx, const int* __restrict__ Cidx, int useMc){
  __shared__ bf16 sAh[128][24], sAl[128][24], sBh[64][24], sBl[64][24];
  int tid = threadIdx.x, warp = tid >> 5, lane = tid & 31;
  int Mr = useMc ? g_mc : M;
  int bm = blockIdx.y*128;
  if (bm >= Mr) return;
  int bn = blockIdx.x*64;
  int wm = (warp >> 1)*32, wn = (warp & 1)*32;

  float c[2][4][4];
  #pragma unroll
  for (int mi = 0; mi < 2; mi++)
    #pragma unroll
    for (int ni = 0; ni < 4; ni++)
      #pragma unroll
      for (int q = 0; q < 4; q++) c[mi][ni][q] = 0.f;

  int arow = tid >> 1, au = (tid & 1) << 3;
  int grA = bm + arow;
  const bf16* pAh = nullptr; const bf16* pAl = nullptr;
  if (grA < Mr){
    int src = Aidx ? Aidx[grA] : grA;
    pAh = Ah + (size_t)src*K;
    pAl = Al + (size_t)src*K;
  }
  int brow = (tid & 127) >> 1, bu = (tid & 1) << 3;
  bool bhi = tid < 128;
  int gnB = bn + brow;
  const bf16* pB = nullptr;
  if (gnB < Ntot) pB = (bhi ? Bh : Bl) + (size_t)gnB*K;

  int nk = K >> 4;
  uint4 zz = make_uint4(0,0,0,0);
  uint4 vAh = zz, vAl = zz, vB = zz;
  if (pAh){ vAh = *(const uint4*)(pAh + au); vAl = *(const uint4*)(pAl + au); }
  if (pB)  vB  = *(const uint4*)(pB + bu);
  *(uint4*)&sAh[arow][au] = vAh;
  *(uint4*)&sAl[arow][au] = vAl;
  if (bhi) *(uint4*)&sBh[brow][bu] = vB; else *(uint4*)&sBl[brow][bu] = vB;
  __syncthreads();

  int r = lane >> 2, kq = (lane & 3) << 1;
  int lq = lane & 7, ts = lane >> 3;
  int aro = lq + ((ts & 1) ? 8 : 0);
  int aco = (ts & 2) ? 8 : 0;
  int bro = lq + ((ts & 2) ? 8 : 0);
  int bco = (ts & 1) ? 8 : 0;
  for (int kc = 0; kc < nk; kc++){
    bool more = (kc + 1 < nk);
    if (more){
      int k0 = (kc + 1) << 4;
      vAh = zz; vAl = zz; vB = zz;
      if (pAh){ vAh = *(const uint4*)(pAh + k0 + au); vAl = *(const uint4*)(pAl + k0 + au); }
      if (pB)  vB  = *(const uint4*)(pB + k0 + bu);
    }
    uint32_t fah[2][4], fal[2][4];
    #pragma unroll
    for (int mi = 0; mi < 2; mi++){
      int rb = wm + mi*16 + aro;
      ldsm_x4(fah[mi], &sAh[rb][aco]);
      ldsm_x4(fal[mi], &sAl[rb][aco]);
    }
    uint32_t fbh[4][2], fbl[4][2];
    #pragma unroll
    for (int np = 0; np < 2; np++){
      int nb = wn + np*16 + bro;
      uint32_t th[4], tl[4];
      ldsm_x4(th, &sBh[nb][bco]);
      ldsm_x4(tl, &sBl[nb][bco]);
      fbh[np*2  ][0] = th[0]; fbh[np*2  ][1] = th[1];
      fbh[np*2+1][0] = th[2]; fbh[np*2+1][1] = th[3];
      fbl[np*2  ][0] = tl[0]; fbl[np*2  ][1] = tl[1];
      fbl[np*2+1][0] = tl[2]; fbl[np*2+1][1] = tl[3];
    }
    #pragma unroll
    for (int mi = 0; mi < 2; mi++)
      #pragma unroll
      for (int ni = 0; ni < 4; ni++){
        MMA_BF16(c[mi][ni], fah[mi], fbh[ni]);
        MMA_BF16(c[mi][ni], fah[mi], fbl[ni]);
        MMA_BF16(c[mi][ni], fal[mi], fbh[ni]);
      }
    if (more){
      __syncthreads();
      *(uint4*)&sAh[arow][au] = vAh;
      *(uint4*)&sAl[arow][au] = vAl;
      if (bhi) *(uint4*)&sBh[brow][bu] = vB; else *(uint4*)&sBl[brow][bu] = vB;
      __syncthreads();
    }
  }

  #pragma unroll
  for (int mi = 0; mi < 2; mi++){
    #pragma unroll
    for (int ni = 0; ni < 4; ni++){
      int col = bn + wn + ni*8 + kq;
      if (col >= Ntot) continue;
      float bx = 0.f, by = 0.f;
      if (bias){ bx = bias[col]; by = bias[col+1]; }
      int row0 = bm + wm + mi*16 + r;
      if (row0 < Mr){
        int cr = Cidx ? Cidx[row0] : row0;
        float2 v = make_float2(c[mi][ni][0] + bx, c[mi][ni][1] + by);
        *(float2*)(C + (size_t)cr*Ntot + col) = v;
      }
      if (row0 + 8 < Mr){
        int cr = Cidx ? Cidx[row0+8] : row0+8;
        float2 v = make_float2(c[mi][ni][2] + bx, c[mi][ni][3] + by);
        *(float2*)(C + (size_t)cr*Ntot + col) = v;
      }
    }
  }
}

// ---- fc_node HMMA GEMM: B from f32 [K][N], split on the fly; ldmatrix loads ----
__global__ void __launch_bounds__(256, 2)
k_hgemm_fcn(const bf16* __restrict__ Ah, const bf16* __restrict__ Al,
            const float* __restrict__ Bf, const float* __restrict__ bias,
            float* __restrict__ C, int M, int Ntot, int K){
  __shared__ bf16 sAh[128][24], sAl[128][24], sBh[64][24], sBl[64][24];
  int tid = threadIdx.x, warp = tid >> 5, lane = tid & 31;
  int bm = 0;
  int bn = blockIdx.x*64;
  int wm = (warp >> 1)*32, wn = (warp & 1)*32;

  float c[2][4][4];
  #pragma unroll
  for (int mi = 0; mi < 2; mi++)
    #pragma unroll
    for (int ni = 0; ni < 4; ni++)
      #pragma unroll
      for (int q = 0; q < 4; q++) c[mi][ni][q] = 0.f;

  int arow = tid >> 1, au = (tid & 1) << 3;
  const bf16* pAh = Ah + (size_t)arow*K;
  const bf16* pAl = Al + (size_t)arow*K;
  int bk = tid >> 4, bn4 = (tid & 15) << 2;
  bool bok = (bn + bn4 < Ntot);

  int nk = K >> 4;
  uint4 vAh, vAl;
  float4 vB = make_float4(0.f,0.f,0.f,0.f);
  vAh = *(const uint4*)(pAh + au);
  vAl = *(const uint4*)(pAl + au);
  if (bok) vB = *(const float4*)(Bf + (size_t)bk*Ntot + bn + bn4);
  *(uint4*)&sAh[arow][au] = vAh;
  *(uint4*)&sAl[arow][au] = vAl;
  {
    float bvals[4] = {vB.x, vB.y, vB.z, vB.w};
    #pragma unroll
    for (int i = 0; i < 4; i++)
      bsplit(bvals[i], &sBh[bn4 + i][bk], &sBl[bn4 + i][bk]);
  }
  __syncthreads();

  int r = lane >> 2, kq = (lane & 3) << 1;
  int lq = lane & 7, ts = lane >> 3;
  int aro = lq + ((ts & 1) ? 8 : 0);
  int aco = (ts & 2) ? 8 : 0;
  int bro = lq + ((ts & 2) ? 8 : 0);
  int bco = (ts & 1) ? 8 : 0;
  for (int kc = 0; kc < nk; kc++){
    bool more = (kc + 1 < nk);
    if (more){
      int k0 = (kc + 1) << 4;
      vAh = *(const uint4*)(pAh + k0 + au);
      vAl = *(const uint4*)(pAl + k0 + au);
      vB = make_float4(0.f,0.f,0.f,0.f);
      if (bok) vB = *(const float4*)(Bf + (size_t)(k0 + bk)*Ntot + bn + bn4);
    }
    uint32_t fah[2][4], fal[2][4], fbh[4][2], fbl[4][2];
    #pragma unroll
    for (int mi = 0; mi < 2; mi++){
      int rb = wm + mi*16 + aro;
      ldsm_x4(fah[mi], &sAh[rb][aco]);
      ldsm_x4(fal[mi], &sAl[rb][aco]);
    }
    #pragma unroll
    for (int np = 0; np < 2; np++){
      int nb = wn + np*16 + bro;
      uint32_t th[4], tl[4];
      ldsm_x4(th, &sBh[nb][bco]);
      ldsm_x4(tl, &sBl[nb][bco]);
      fbh[np*2  ][0] = th[0]; fbh[np*2  ][1] = th[1];
      fbh[np*2+1][0] = th[2]; fbh[np*2+1][1] = th[3];
      fbl[np*2  ][0] = tl[0]; fbl[np*2  ][1] = tl[1];
      fbl[np*2+1][0] = tl[2]; fbl[np*2+1][1] = tl[3];
    }
    #pragma unroll
    for (int mi = 0; mi < 2; mi++)
      #pragma unroll
      for (int ni = 0; ni < 4; ni++){
        MMA_BF16(c[mi][ni], fah[mi], fbh[ni]);
        MMA_BF16(c[mi][ni], fah[mi], fbl[ni]);
        MMA_BF16(c[mi][ni], fal[mi], fbh[ni]);
      }
    if (more){
      __syncthreads();
      *(uint4*)&sAh[arow][au] = vAh;
      *(uint4*)&sAl[arow][au] = vAl;
      float bvals[4] = {vB.x, vB.y, vB.z, vB.w};
      #pragma unroll
      for (int i = 0; i < 4; i++)
        bsplit(bvals[i], &sBh[bn4 + i][bk], &sBl[bn4 + i][bk]);
      __syncthreads();
    }
  }

  #pragma unroll
  for (int mi = 0; mi < 2; mi++){
    #pragma unroll
    for (int ni = 0; ni < 4; ni++){
      int col = bn + wn + ni*8 + kq;
      if (col >= Ntot) continue;
      float bx = bias[col], by = bias[col+1];
      int row0 = bm + wm + mi*16 + r;
      float2 v0 = make_float2(c[mi][ni][0] + bx, c[mi][ni][1] + by);
      *(float2*)(C + (size_t)row0*Ntot + col) = v0;
      float2 v1 = make_float2(c[mi][ni][2] + bx, c[mi][ni][3] + by);
      *(float2*)(C + (size_t)(row0+8)*Ntot + col) = v1;
    }
  }
}

// ---------------- scalar SGEMM (fc_sp only) ----------------
__global__ void k_gemm(const float* __restrict__ A, const float* __restrict__ B,
                       const float* __restrict__ bias, float* __restrict__ C,
                       int M, int N, int K){
  __shared__ float As[16][64];
  __shared__ float Bs[16][64];
  int bn = blockIdx.x*64, bm = blockIdx.y*64;
  int tid = threadIdx.x;
  int tx = tid & 15, ty = tid >> 4;
  float acc[4][4];
  #pragma unroll
  for (int i = 0; i < 4; i++)
    #pragma unroll
    for (int j = 0; j < 4; j++) acc[i][j] = 0.f;
  int ar = tid >> 2, ak = (tid & 3) << 2;
  int bk = tid >> 4, bn2 = (tid & 15) << 2;
  for (int k0 = 0; k0 < K; k0 += 16){
    float4 av = make_float4(0.f,0.f,0.f,0.f);
    if (bm + ar < M) av = *(const float4*)(A + (size_t)(bm + ar)*K + k0 + ak);
    As[ak  ][ar] = av.x; As[ak+1][ar] = av.y; As[ak+2][ar] = av.z; As[ak+3][ar] = av.w;
    float4 bv = make_float4(0.f,0.f,0.f,0.f);
    if (bn + bn2 < N) bv = *(const float4*)(B + (size_t)(k0 + bk)*N + bn + bn2);
    *(float4*)&Bs[bk][bn2] = bv;
    __syncthreads();
    #pragma unroll
    for (int kk = 0; kk < 16; kk++){
      float4 ra = *(const float4*)&As[kk][ty << 2];
      float4 rb = *(const float4*)&Bs[kk][tx << 2];
      acc[0][0] += ra.x*rb.x; acc[0][1] += ra.x*rb.y; acc[0][2] += ra.x*rb.z; acc[0][3] += ra.x*rb.w;
      acc[1][0] += ra.y*rb.x; acc[1][1] += ra.y*rb.y; acc[1][2] += ra.y*rb.z; acc[1][3] += ra.y*rb.w;
      acc[2][0] += ra.z*rb.x; acc[2][1] += ra.z*rb.y; acc[2][2] += ra.z*rb.z; acc[2][3] += ra.z*rb.w;
      acc[3][0] += ra.w*rb.x; acc[3][1] += ra.w*rb.y; acc[3][2] += ra.w*rb.z; acc[3][3] += ra.w*rb.w;
    }
    __syncthreads();
  }
  #pragma unroll
  for (int i = 0; i < 4; i++){
    int row = bm + (ty << 2) + i;
    if (row >= M) continue;
    #pragma unroll
    for (int j = 0; j < 4; j++){
      int col = bn + (tx << 2) + j;
      if (col >= N) continue;
      float v = acc[i][j];
      if (bias) v += bias[col];
      C[(size_t)row*N + col] = v;
    }
  }
}

// ---------------- attention dots ----------------
__global__ void k_attdot1(const float* __restrict__ aw_s, const float* __restrict__ aw_d){
  int i = blockIdx.x*256 + threadIdx.x;
  if (i >= NN*4) return;
  int n = i >> 2, h = i & 3;
  const float4* hp = (const float4*)(g_h1 + n*256 + h*64);
  const float4* sw = (const float4*)(aw_s + h*64);
  const float4* dw = (const float4*)(aw_d + h*64);
  float s = 0.f, d = 0.f;
  #pragma unroll
  for (int j = 0; j < 16; j++){
    float4 x = hp[j], a = sw[j], b = dw[j];
    s += x.x*a.x + x.y*a.y + x.z*a.z + x.w*a.w;
    d += x.x*b.x + x.y*b.y + x.z*b.z + x.w*b.w;
  }
  g_as1[i] = s; g_ad1[i] = d;
}
__global__ void k_attdot2(const float* __restrict__ aw_s, const float* __restrict__ aw_d){
  int n = blockIdx.x*256 + threadIdx.x;
  if (n >= NN) return;
  const float4* hp = (const float4*)(g_h2 + n*128);
  const float4* sw = (const float4*)aw_s;
  const float4* dw = (const float4*)aw_d;
  float s = 0.f, d = 0.f;
  #pragma unroll
  for (int j = 0; j < 32; j++){
    float4 x = hp[j], a = sw[j], b = dw[j];
    s += x.x*a.x + x.y*a.y + x.z*a.z + x.w*a.w;
    d += x.x*b.x + x.y*b.y + x.z*b.z + x.w*b.w;
  }
  g_as2[n] = s; g_ad2[n] = d;
}

// ---------------- edge softmax + aggregation, layer 1 -> z1 bf16 split ----------------
__global__ void k_agg1(const float* __restrict__ bias){
  int wid = threadIdx.x >> 5, lane = threadIdx.x & 31;
  int n = blockIdx.x*8 + wid;
  int r0 = g_rowptr[n], r1 = g_rowptr[n+1];
  float4 ad = *(const float4*)(g_ad1 + n*4);
  float m0 = -1e30f, m1 = -1e30f, m2 = -1e30f, m3 = -1e30f;
  for (int e = r0 + lane; e < r1; e += 32){
    int s = g_srcs[e];
    float4 as = *(const float4*)(g_as1 + s*4);
    float v0 = as.x + ad.x; v0 = v0 > 0.f ? v0 : 0.2f*v0;
    float v1 = as.y + ad.y; v1 = v1 > 0.f ? v1 : 0.2f*v1;
    float v2 = as.z + ad.z; v2 = v2 > 0.f ? v2 : 0.2f*v2;
    float v3 = as.w + ad.w; v3 = v3 > 0.f ? v3 : 0.2f*v3;
    m0 = fmaxf(m0, v0); m1 = fmaxf(m1, v1); m2 = fmaxf(m2, v2); m3 = fmaxf(m3, v3);
  }
  #pragma unroll
  for (int o = 16; o; o >>= 1){
    m0 = fmaxf(m0, __shfl_xor_sync(0xffffffffu, m0, o));
    m1 = fmaxf(m1, __shfl_xor_sync(0xffffffffu, m1, o));
    m2 = fmaxf(m2, __shfl_xor_sync(0xffffffffu, m2, o));
    m3 = fmaxf(m3, __shfl_xor_sync(0xffffffffu, m3, o));
  }
  float s0 = 0.f, s1 = 0.f, s2 = 0.f, s3 = 0.f;
  for (int e = r0 + lane; e < r1; e += 32){
    int s = g_srcs[e];
    float4 as = *(const float4*)(g_as1 + s*4);
    float v0 = as.x + ad.x; v0 = v0 > 0.f ? v0 : 0.2f*v0;
    float v1 = as.y + ad.y; v1 = v1 > 0.f ? v1 : 0.2f*v1;
    float v2 = as.z + ad.z; v2 = v2 > 0.f ? v2 : 0.2f*v2;
    float v3 = as.w + ad.w; v3 = v3 > 0.f ? v3 : 0.2f*v3;
    s0 += __expf(v0 - m0); s1 += __expf(v1 - m1);
    s2 += __expf(v2 - m2); s3 += __expf(v3 - m3);
  }
  #pragma unroll
  for (int o = 16; o; o >>= 1){
    s0 += __shfl_xor_sync(0xffffffffu, s0, o);
    s1 += __shfl_xor_sync(0xffffffffu, s1, o);
    s2 += __shfl_xor_sync(0xffffffffu, s2, o);
    s3 += __shfl_xor_sync(0xffffffffu, s3, o);
  }
  int hsel = lane >> 3;
  float mh  = hsel == 0 ? m0 : hsel == 1 ? m1 : hsel == 2 ? m2 : m3;
  float inv = 1.f / (hsel == 0 ? s0 : hsel == 1 ? s1 : hsel == 2 ? s2 : s3);
  float adh = hsel == 0 ? ad.x : hsel == 1 ? ad.y : hsel == 2 ? ad.z : ad.w;
  float a0=0,a1=0,a2=0,a3=0,a4=0,a5=0,a6=0,a7=0;
  for (int e = r0; e < r1; e++){
    int s = g_srcs[e];
    float v = g_as1[s*4 + hsel] + adh; v = v > 0.f ? v : 0.2f*v;
    float alpha = __expf(v - mh) * inv;
    const float4* xp = (const float4*)(g_h1 + s*256 + lane*8);
    float4 x0 = xp[0], x1 = xp[1];
    a0 += alpha*x0.x; a1 += alpha*x0.y; a2 += alpha*x0.z; a3 += alpha*x0.w;
    a4 += alpha*x1.x; a5 += alpha*x1.y; a6 += alpha*x1.z; a7 += alpha*x1.w;
  }
  int cb = lane*8;
  float r[8] = {a0,a1,a2,a3,a4,a5,a6,a7};
  #pragma unroll
  for (int i = 0; i < 8; i++){
    float o = r[i] + bias[cb + i];
    o = o > 0.f ? o : expm1f(o);                           // ELU
    bsplit(o, &g_z1h[n*256 + cb + i], &g_z1l[n*256 + cb + i]);
  }
}

// ---------------- edge softmax + aggregation, layer 2 -> z2 bf16 split ----------------
__global__ void k_agg2(const float* __restrict__ bias){
  int wid = threadIdx.x >> 5, lane = threadIdx.x & 31;
  int n = blockIdx.x*8 + wid;
  int r0 = g_rowptr[n], r1 = g_rowptr[n+1];
  float ad = g_ad2[n];
  float m = -1e30f;
  for (int e = r0 + lane; e < r1; e += 32){
    float v = g_as2[g_srcs[e]] + ad; v = v > 0.f ? v : 0.2f*v;
    m = fmaxf(m, v);
  }
  #pragma unroll
  for (int o = 16; o; o >>= 1) m = fmaxf(m, __shfl_xor_sync(0xffffffffu, m, o));
  float ssum = 0.f;
  for (int e = r0 + lane; e < r1; e += 32){
    float v = g_as2[g_srcs[e]] + ad; v = v > 0.f ? v : 0.2f*v;
    ssum += __expf(v - m);
  }
  #pragma unroll
  for (int o = 16; o; o >>= 1) ssum += __shfl_xor_sync(0xffffffffu, ssum, o);
  float inv = 1.f / ssum;
  float a0=0,a1=0,a2=0,a3=0;
  for (int e = r0; e < r1; e++){
    int s = g_srcs[e];
    float v = g_as2[s] + ad; v = v > 0.f ? v : 0.2f*v;
    float alpha = __expf(v - m) * inv;
    float4 x = *(const float4*)(g_h2 + s*128 + lane*4);
    a0 += alpha*x.x; a1 += alpha*x.y; a2 += alpha*x.z; a3 += alpha*x.w;
  }
  int cb = lane*4;
  float rr[4] = {a0 + bias[cb], a1 + bias[cb+1], a2 + bias[cb+2], a3 + bias[cb+3]};
  #pragma unroll
  for (int i = 0; i < 4; i++)
    bsplit(rr[i], &g_z2h[n*128 + cb + i], &g_z2l[n*128 + cb + i]);
}

// ---------------- BiLSTM recurrence ----------------
__global__ void __launch_bounds__(512, 1)
k_lstm(const float* __restrict__ whhf, const float* __restrict__ whhb,
       const int* __restrict__ lengths){
  extern __shared__ char smraw[];
  ull*   ws  = (ull*)smraw;
  float* hsm = (float*)(ws + 512*33);
  float* gsm = hsm + 256;
  int g   = threadIdx.x;
  int dir = blockIdx.y;
  int b0  = blockIdx.x*2;
  const float* whh = dir ? whhb : whhf;
  const ull* wrow = (const ull*)(whh + g*128);
  ull wreg[32];
  #pragma unroll
  for (int j = 0; j < 32; j++) wreg[j] = wrow[j];
  #pragma unroll
  for (int j = 0; j < 32; j++) ws[g*33 + j] = wrow[32 + j];
  if (g < 256) hsm[g] = 0.f;
  float cc = 0.f;
  int len0 = lengths[b0], len1 = lengths[b0+1];
  int Tn = len0 > len1 ? len0 : len1;
  const float* x0p = g_xproj[dir] + (size_t)b0*TT*512;
  const float* x1p = x0p + (size_t)TT*512;
  __syncthreads();
  for (int t = 0; t < Tn; t++){
    float xv0 = x0p[t*512 + g];
    float xv1 = x1p[t*512 + g];
    ull a0 = 0ULL, a1 = 0ULL;
    const ull* h0p = (const ull*)hsm;
    const ull* h1p = (const ull*)(hsm + 128);
    #pragma unroll
    for (int j = 0; j < 32; j++){
      ull w = wreg[j];
      a0 = fma2(w, h0p[j], a0);
      a1 = fma2(w, h1p[j], a1);
    }
    #pragma unroll
    for (int j = 0; j < 32; j++){
      ull w = ws[g*33 + j];
      a0 = fma2(w, h0p[32 + j], a0);
      a1 = fma2(w, h1p[32 + j], a1);
    }
    gsm[g]       = hsum2(a0) + xv0;
    gsm[512 + g] = hsum2(a1) + xv1;
    __syncthreads();
    if (g < 256){
      int b = g >> 7, j = g & 127;
      const float* gb = gsm + b*512;
      float gi = gb[j], gf = gb[128 + j], gg = gb[256 + j], go = gb[384 + j];
      cc = sigf(gf)*cc + sigf(gi)*tanhf(gg);
      float h = sigf(go)*tanhf(cc);
      hsm[b*128 + j] = h;
      int L = b ? len1 : len0;
      if (dir == 0){
        if (t < L) g_lstm[((size_t)(b0 + b)*TT + t)*256 + j] = h;
      } else {
        if (t < L) g_lstm[((size_t)(b0 + b)*TT + (L - 1 - t))*256 + 128 + j] = h;
      }
    }
    __syncthreads();
  }
}

// ---------------- masked attention pooling ----------------
__global__ void k_attnpool(const float* __restrict__ wn, const float* __restrict__ bn,
                           const float* __restrict__ wsp, const float* __restrict__ bsp,
                           const int* __restrict__ lengths){
  __shared__ float sc[256];
  __shared__ float red[256];
  int b = blockIdx.x, p = blockIdx.y;
  const float* w = p ? wsp : wn;
  float bias = p ? bsp[0] : bn[0];
  int tid = threadIdx.x;
  int len = lengths[b];
  float sv = -1e30f;
  if (tid < TT && tid < len){
    const float4* row = (const float4*)(g_lstm + ((size_t)b*TT + tid)*256);
    const float4* wv = (const float4*)w;
    float s = 0.f;
    #pragma unroll
    for (int j = 0; j < 64; j++){
      float4 x = row[j], y = wv[j];
      s += x.x*y.x + x.y*y.y + x.z*y.z + x.w*y.w;
    }
    sv = s + bias;
  }
  red[tid] = sv;
  __syncthreads();
  #pragma unroll
  for (int o = 128; o; o >>= 1){ if (tid < o) red[tid] = fmaxf(red[tid], red[tid+o]); __syncthreads(); }
  float m = red[0];
  __syncthreads();
  float e = (sv <= -1e29f) ? 0.f : __expf(sv - m);
  sc[tid] = e; red[tid] = e;
  __syncthreads();
  #pragma unroll
  for (int o = 128; o; o >>= 1){ if (tid < o) red[tid] += red[tid+o]; __syncthreads(); }
  float inv = 1.f / red[0];
  float acc = 0.f;
  for (int t = 0; t < TT; t++)
    acc += sc[t] * g_lstm[((size_t)b*TT + t)*256 + tid];
  float v = acc * inv;
  g_ctx[p][b*256 + tid] = v;
  if (p == 0) bsplit(v, &g_cxh[b*256 + tid], &g_cxl[b*256 + tid]);
}

// ---------------- launch ----------------
extern "C" void kernel_launch(void* const* d_in, const int* in_sizes, int n_in,
                              void* d_out, int out_size){
  const float* xc   = (const float*)d_in[0];
  const float* tf   = (const float*)d_in[1];
  const float* emb  = (const float*)d_in[2];
  const float* g1W  = (const float*)d_in[3];
  const float* g1as = (const float*)d_in[4];
  const float* g1ad = (const float*)d_in[5];
  const float* g1b  = (const float*)d_in[6];
  const float* g2W  = (const float*)d_in[7];
  const float* g2as = (const float*)d_in[8];
  const float* g2ad = (const float*)d_in[9];
  const float* g2b  = (const float*)d_in[10];
  const float* wihf = (const float*)d_in[11];
  const float* whhf = (const float*)d_in[12];
  const float* bf   = (const float*)d_in[13];
  const float* wihb = (const float*)d_in[14];
  const float* whhb = (const float*)d_in[15];
  const float* bb   = (const float*)d_in[16];
  const float* anw  = (const float*)d_in[17];
  const float* anb  = (const float*)d_in[18];
  const float* asw  = (const float*)d_in[19];
  const float* asb  = (const float*)d_in[20];
  const float* fnW  = (const float*)d_in[21];
  const float* fnb  = (const float*)d_in[22];
  const float* fsW  = (const float*)d_in[23];
  const float* fsb  = (const float*)d_in[24];
  const int*   ei   = (const int*)d_in[25];
  const int*   seq  = (const int*)d_in[26];
  const int*   len  = (const int*)d_in[27];
  float* out = (float*)d_out;

  float *p_h1, *p_h2, *p_xp, *p_ctx, *p_lstm;
  int *p_af, *p_ab, *p_ci;
  bf16 *p_nfh, *p_nfl, *p_w1h, *p_w1l, *p_z1h, *p_z1l, *p_w2h, *p_w2l;
  bf16 *p_z2h, *p_z2l, *p_wih, *p_cxh, *p_cxl;
  cudaGetSymbolAddress((void**)&p_h1,  g_h1);
  cudaGetSymbolAddress((void**)&p_h2,  g_h2);
  cudaGetSymbolAddress((void**)&p_xp,  g_xproj);
  cudaGetSymbolAddress((void**)&p_ctx, g_ctx);
  cudaGetSymbolAddress((void**)&p_lstm, g_lstm);
  cudaGetSymbolAddress((void**)&p_af,  g_aidxf);
  cudaGetSymbolAddress((void**)&p_ab,  g_aidxb);
  cudaGetSymbolAddress((void**)&p_ci,  g_cidx);
  cudaGetSymbolAddress((void**)&p_nfh, g_nfh);
  cudaGetSymbolAddress((void**)&p_nfl, g_nfl);
  cudaGetSymbolAddress((void**)&p_w1h, g_w1h);
  cudaGetSymbolAddress((void**)&p_w1l, g_w1l);
  cudaGetSymbolAddress((void**)&p_z1h, g_z1h);
  cudaGetSymbolAddress((void**)&p_z1l, g_z1l);
  cudaGetSymbolAddress((void**)&p_w2h, g_w2h);
  cudaGetSymbolAddress((void**)&p_w2l, g_w2l);
  cudaGetSymbolAddress((void**)&p_z2h, g_z2h);
  cudaGetSymbolAddress((void**)&p_z2l, g_z2l);
  cudaGetSymbolAddress((void**)&p_wih, g_wih);
  cudaGetSymbolAddress((void**)&p_cxh, g_cxh);
  cudaGetSymbolAddress((void**)&p_cxl, g_cxl);

  int lstm_smem = 512*33*8 + 256*4 + 1024*4;
  cudaFuncSetAttribute(k_lstm, cudaFuncAttributeMaxDynamicSharedMemorySize, lstm_smem);

  // fork a side stream for the independent CSR/index chain (capture-legal pattern)
  cudaStream_t s2;
  cudaStreamCreateWithFlags(&s2, cudaStreamNonBlocking);
  cudaEvent_t evFork, evJoin;
  cudaEventCreateWithFlags(&evFork, cudaEventDisableTiming);
  cudaEventCreateWithFlags(&evJoin, cudaEventDisableTiming);
  cudaEventRecord(evFork, 0);
  cudaStreamWaitEvent(s2, evFork, 0);

  // side stream: CSR build + sequence indexing + lstm zero
  k_zero_cnt<<<(NN+255)/256, 256, 0, s2>>>();
  k_count<<<(ET+255)/256, 256, 0, s2>>>(ei);
  k_scan<<<1, 1024, 0, s2>>>();
  k_scatter<<<(ET+255)/256, 256, 0, s2>>>(ei);
  k_sortseg<<<2500, 256, 0, s2>>>(ei);
  k_seqidx<<<BB, 256, 0, s2>>>(seq, len);
  cudaMemsetAsync(p_lstm, 0, (size_t)BB*TT*256*sizeof(float), s2);

  // main stream: prep + weight splits + GAT1 GEMM + attdot1
  k_prep<<<11250, 256>>>(xc, tf, emb, wihf, wihb);
  k_tsplit<<<dim3(8, 5),  dim3(32,32)>>>(g1W, p_w1h, p_w1l, 134, 256, 144);
  k_tsplit<<<dim3(4, 8),  dim3(32,32)>>>(g2W, p_w2h, p_w2l, 256, 128, 256);
  k_hgemm<<<dim3(4, 157), 256>>>(p_nfh, p_nfl, p_w1h, p_w1l,
      nullptr, p_h1, NN, 256, 144, nullptr, nullptr, 0);
  k_attdot1<<<(NN*4+255)/256, 256>>>(g1as, g1ad);

  // join: agg1 needs both branches
  cudaEventRecord(evJoin, s2);
  cudaStreamWaitEvent(0, evJoin, 0);

  k_agg1<<<2500, 256>>>(g1b);

  // GAT layer 2
  k_hgemm<<<dim3(2, 157), 256>>>(p_z1h, p_z1l, p_w2h, p_w2l,
      nullptr, p_h2, NN, 128, 256, nullptr, nullptr, 0);
  k_attdot2<<<(NN+255)/256, 256>>>(g2as, g2ad);
  k_agg2<<<2500, 256>>>(g2b);

  // x-projections over valid rows
  k_hgemm<<<dim3(8, 200), 256>>>(p_z2h, p_z2l, p_wih,             p_wih + 512*128,
      bf, p_xp,                      BB*TT, 512, 128, p_af, p_ci, 1);
  k_hgemm<<<dim3(8, 200), 256>>>(p_z2h, p_z2l, p_wih + 2*512*128, p_wih + 3*512*128,
      bb, p_xp + (size_t)BB*TT*512,  BB*TT, 512, 128, p_ab, p_ci, 1);

  // BiLSTM
  k_lstm<<<dim3(64, 2), 512, lstm_smem>>>(whhf, whhb, len);

  // attention pooling + output heads
  k_attnpool<<<dim3(BB, 2), 256>>>(anw, anb, asw, asb, len);
  k_hgemm_fcn<<<313, 256>>>(p_cxh, p_cxl, fnW, fnb, out, BB, 20000, 256);
  k_gemm<<<dim3(1, 2), 256>>>(p_ctx + BB*256, fsW, fsb, out + (size_t)BB*20000, BB, 64, 256);

  cudaEventDestroy(evFork);
  cudaEventDestroy(evJoin);
  cudaStreamDestroy(s2);
}

// round 16
// speedup vs baseline: 1.0709x; 1.0211x over previous
#include <cuda_runtime.h>
#include <cuda_bf16.h>
#include <cstdint>

typedef unsigned long long ull;
typedef __nv_bfloat16 bf16;

#define NN 20000
#define NE 320000
#define ET (NE+NN)
#define BB 128
#define TT 200

__device__ __forceinline__ ull fma2(ull a, ull b, ull c){
  ull d; asm("fma.rn.f32x2 %0, %1, %2, %3;" : "=l"(d) : "l"(a), "l"(b), "l"(c)); return d;
}
__device__ __forceinline__ float hsum2(ull v){
  float lo, hi; asm("mov.b64 {%0, %1}, %2;" : "=f"(lo), "=f"(hi) : "l"(v)); return lo + hi;
}
__device__ __forceinline__ float sigf(float x){ return 1.f/(1.f+__expf(-x)); }

__device__ __forceinline__ void bsplit(float x, bf16* h, bf16* l){
  bf16 hb = __float2bfloat16(x);
  *h = hb;
  *l = __float2bfloat16(x - __bfloat162float(hb));
}

#define MMA_BF16(C, A, B) \
  asm volatile("mma.sync.aligned.m16n8k16.row.col.f32.bf16.bf16.f32 " \
    "{%0,%1,%2,%3}, {%4,%5,%6,%7}, {%8,%9}, {%0,%1,%2,%3};" \
    : "+f"((C)[0]), "+f"((C)[1]), "+f"((C)[2]), "+f"((C)[3]) \
    : "r"((A)[0]), "r"((A)[1]), "r"((A)[2]), "r"((A)[3]), "r"((B)[0]), "r"((B)[1]))

__device__ __forceinline__ void ldsm_x4(uint32_t* r, const void* p){
  uint32_t a = (uint32_t)__cvta_generic_to_shared(p);
  asm volatile("ldmatrix.sync.aligned.m8n8.x4.shared.b16 {%0,%1,%2,%3}, [%4];"
    : "=r"(r[0]), "=r"(r[1]), "=r"(r[2]), "=r"(r[3]) : "r"(a));
}

// ---------------- scratch (device globals; no allocs) ----------------
__device__ float g_h1[NN*256];
__device__ float g_h2[NN*128];
__device__ float g_as1[NN*4];
__device__ float g_ad1[NN*4];
__device__ float g_as2[NN];
__device__ float g_ad2[NN];
__device__ int   g_cnt[NN];
__device__ int   g_fill[NN];
__device__ int   g_rowptr[NN+1];
__device__ int   g_srcs[ET];
__device__ float g_xproj[2][(size_t)BB*TT*512];
__device__ float g_lstm[BB*TT*256];
__device__ float g_ctx[2][BB*256];
__device__ int   g_aidxf[BB*TT];
__device__ int   g_aidxb[BB*TT];
__device__ int   g_cidx[BB*TT];
__device__ int   g_mc;
// bf16 split operand buffers
__device__ bf16 g_nfh[NN*144],  g_nfl[NN*144];
__device__ bf16 g_w1h[256*144], g_w1l[256*144];
__device__ bf16 g_z1h[NN*256],  g_z1l[NN*256];
__device__ bf16 g_w2h[128*256], g_w2l[128*256];
__device__ bf16 g_z2h[NN*128],  g_z2l[NN*128];
__device__ bf16 g_wih[2][2][512*128];
__device__ bf16 g_cxh[BB*256],  g_cxl[BB*256];

// ---------------- prep ----------------
__global__ void k_prep(const float* __restrict__ xc, const float* __restrict__ tf,
                       const float* __restrict__ emb,
                       const float* __restrict__ wihf, const float* __restrict__ wihb){
  int i = blockIdx.x*256 + threadIdx.x;
  if (i < NN*144){
    int r = i/144, c = i - r*144;
    float v = 0.f;
    if (c < 2)        v = xc[r*2 + c];
    else if (c < 130) v = emb[r*128 + (c-2)];
    else if (c < 134) v = tf[r*4 + (c-130)];
    bsplit(v, &g_nfh[i], &g_nfl[i]);
  }
  if (i < 512*128){
    bsplit(wihf[i], &g_wih[0][0][i], &g_wih[0][1][i]);
    bsplit(wihb[i], &g_wih[1][0][i], &g_wih[1][1][i]);
  }
}

// ---------------- transpose + bf16 split ----------------
__global__ void k_tsplit(const float* __restrict__ src, bf16* __restrict__ dh,
                         bf16* __restrict__ dl, int Ks, int Ns, int Kp){
  __shared__ float t[32][33];
  int n0 = blockIdx.x*32, k0 = blockIdx.y*32;
  int tx = threadIdx.x, ty = threadIdx.y;
  int k = k0 + ty, n = n0 + tx;
  t[ty][tx] = (k < Ks && n < Ns) ? src[(size_t)k*Ns + n] : 0.f;
  __syncthreads();
  int nn = n0 + ty, kk = k0 + tx;
  if (nn < Ns && kk < Kp){
    float v = t[tx][ty];
    bsplit(v, &dh[(size_t)nn*Kp + kk], &dl[(size_t)nn*Kp + kk]);
  }
}

// ---------------- compact valid (b,t) rows ----------------
__global__ void k_seqidx(const int* __restrict__ seq, const int* __restrict__ lengths){
  __shared__ int red[256];
  int b = blockIdx.x, tid = threadIdx.x;
  red[tid] = (tid < b) ? lengths[tid] : 0;
  __syncthreads();
  #pragma unroll
  for (int o = 128; o; o >>= 1){ if (tid < o) red[tid] += red[tid+o]; __syncthreads(); }
  int off = red[0];
  int len = lengths[b];
  for (int t = tid; t < len; t += 256){
    g_aidxf[off+t] = seq[b*TT + t];
    g_aidxb[off+t] = seq[b*TT + (len-1-t)];
    g_cidx[off+t]  = b*TT + t;
  }
  if (b == BB-1 && tid == 0) g_mc = off + len;
}

// ---------------- CSR build ----------------
__global__ void k_zero_cnt(){
  int i = blockIdx.x*256 + threadIdx.x;
  if (i < NN){ g_cnt[i] = 0; g_fill[i] = 0; }
}
__global__ void k_count(const int* __restrict__ ei){
  int e = blockIdx.x*256 + threadIdx.x;
  if (e >= ET) return;
  int d = (e < NE) ? ei[NE + e] : (e - NE);
  atomicAdd(&g_cnt[d], 1);
}
__global__ void k_scan(){
  __shared__ int ps[1024];
  int tid = threadIdx.x;
  int base = tid*20;
  int sum = 0;
  for (int j = 0; j < 20; j++){ int i = base + j; if (i < NN) sum += g_cnt[i]; }
  ps[tid] = sum;
  __syncthreads();
  for (int off = 1; off < 1024; off <<= 1){
    int v = (tid >= off) ? ps[tid-off] : 0;
    __syncthreads();
    ps[tid] += v;
    __syncthreads();
  }
  int run = ps[tid] - sum;
  for (int j = 0; j < 20; j++){ int i = base + j; if (i < NN){ g_rowptr[i] = run; run += g_cnt[i]; } }
  if (tid == 0) g_rowptr[NN] = ET;
}
__global__ void k_scatter(const int* __restrict__ ei){
  int e = blockIdx.x*256 + threadIdx.x;
  if (e >= ET) return;
  int d = (e < NE) ? ei[NE + e] : (e - NE);
  int p = atomicAdd(&g_fill[d], 1);
  g_srcs[g_rowptr[d] + p] = e;
}
__global__ void k_sortseg(const int* __restrict__ ei){
  __shared__ int buf[8][128];
  int wid = threadIdx.x >> 5, lane = threadIdx.x & 31;
  int n = blockIdx.x*8 + wid;
  if (n >= NN) return;
  int r0 = g_rowptr[n], r1 = g_rowptr[n+1], d = r1 - r0;
  if (d <= 128){
    for (int j = lane; j < d; j += 32) buf[wid][j] = g_srcs[r0 + j];
    __syncwarp();
    if (lane == 0){
      for (int a = 1; a < d; a++){
        int v = buf[wid][a]; int b = a - 1;
        while (b >= 0 && buf[wid][b] > v){ buf[wid][b+1] = buf[wid][b]; b--; }
        buf[wid][b+1] = v;
      }
    }
    __syncwarp();
    for (int j = lane; j < d; j += 32){
      int id = buf[wid][j];
      g_srcs[r0 + j] = (id < NE) ? ei[id] : (id - NE);
    }
  } else {
    for (int j = lane; j < d; j += 32){
      int id = g_srcs[r0 + j];
      g_srcs[r0 + j] = (id < NE) ? ei[id] : (id - NE);
    }
  }
}

// ---- bf16-split HMMA GEMM with ldmatrix fragment loads ----
__global__ void __launch_bounds__(256, 2)
k_hgemm(const bf16* __restrict__ Ah, const bf16* __restrict__ Al,
        const bf16* __restrict__ Bh, const bf16* __restrict__ Bl,
        const float* __restrict__ bias, float* __restrict__ C,
        int M, int Ntot, int K,
        const int* __restrict__ Aidx, const int* __restrict__ Cidx, int useMc){
  __shared__ bf16 sAh[128][24], sAl[128][24], sBh[64][24], sBl[64][24];
  int tid = threadIdx.x, warp = tid >> 5, lane = tid & 31;
  int Mr = useMc ? g_mc : M;
  int bm = blockIdx.y*128;
  if (bm >= Mr) return;
  int bn = blockIdx.x*64;
  int wm = (warp >> 1)*32, wn = (warp & 1)*32;

  float c[2][4][4];
  #pragma unroll
  for (int mi = 0; mi < 2; mi++)
    #pragma unroll
    for (int ni = 0; ni < 4; ni++)
      #pragma unroll
      for (int q = 0; q < 4; q++) c[mi][ni][q] = 0.f;

  int arow = tid >> 1, au = (tid & 1) << 3;
  int grA = bm + arow;
  const bf16* pAh = nullptr; const bf16* pAl = nullptr;
  if (grA < Mr){
    int src = Aidx ? Aidx[grA] : grA;
    pAh = Ah + (size_t)src*K;
    pAl = Al + (size_t)src*K;
  }
  int brow = (tid & 127) >> 1, bu = (tid & 1) << 3;
  bool bhi = tid < 128;
  int gnB = bn + brow;
  const bf16* pB = nullptr;
  if (gnB < Ntot) pB = (bhi ? Bh : Bl) + (size_t)gnB*K;

  int nk = K >> 4;
  uint4 zz = make_uint4(0,0,0,0);
  uint4 vAh = zz, vAl = zz, vB = zz;
  if (pAh){ vAh = *(const uint4*)(pAh + au); vAl = *(const uint4*)(pAl + au); }
  if (pB)  vB  = *(const uint4*)(pB + bu);
  *(uint4*)&sAh[arow][au] = vAh;
  *(uint4*)&sAl[arow][au] = vAl;
  if (bhi) *(uint4*)&sBh[brow][bu] = vB; else *(uint4*)&sBl[brow][bu] = vB;
  __syncthreads();

  int r = lane >> 2, kq = (lane & 3) << 1;
  int lq = lane & 7, ts = lane >> 3;
  int aro = lq + ((ts & 1) ? 8 : 0);
  int aco = (ts & 2) ? 8 : 0;
  int bro = lq + ((ts & 2) ? 8 : 0);
  int bco = (ts & 1) ? 8 : 0;
  for (int kc = 0; kc < nk; kc++){
    bool more = (kc + 1 < nk);
    if (more){
      int k0 = (kc + 1) << 4;
      vAh = zz; vAl = zz; vB = zz;
      if (pAh){ vAh = *(const uint4*)(pAh + k0 + au); vAl = *(const uint4*)(pAl + k0 + au); }
      if (pB)  vB  = *(const uint4*)(pB + k0 + bu);
    }
    uint32_t fah[2][4], fal[2][4];
    #pragma unroll
    for (int mi = 0; mi < 2; mi++){
      int rb = wm + mi*16 + aro;
      ldsm_x4(fah[mi], &sAh[rb][aco]);
      ldsm_x4(fal[mi], &sAl[rb][aco]);
    }
    uint32_t fbh[4][2], fbl[4][2];
    #pragma unroll
    for (int np = 0; np < 2; np++){
      int nb = wn + np*16 + bro;
      uint32_t th[4], tl[4];
      ldsm_x4(th, &sBh[nb][bco]);
      ldsm_x4(tl, &sBl[nb][bco]);
      fbh[np*2  ][0] = th[0]; fbh[np*2  ][1] = th[1];
      fbh[np*2+1][0] = th[2]; fbh[np*2+1][1] = th[3];
      fbl[np*2  ][0] = tl[0]; fbl[np*2  ][1] = tl[1];
      fbl[np*2+1][0] = tl[2]; fbl[np*2+1][1] = tl[3];
    }
    #pragma unroll
    for (int mi = 0; mi < 2; mi++)
      #pragma unroll
      for (int ni = 0; ni < 4; ni++){
        MMA_BF16(c[mi][ni], fah[mi], fbh[ni]);
        MMA_BF16(c[mi][ni], fah[mi], fbl[ni]);
        MMA_BF16(c[mi][ni], fal[mi], fbh[ni]);
      }
    if (more){
      __syncthreads();
      *(uint4*)&sAh[arow][au] = vAh;
      *(uint4*)&sAl[arow][au] = vAl;
      if (bhi) *(uint4*)&sBh[brow][bu] = vB; else *(uint4*)&sBl[brow][bu] = vB;
      __syncthreads();
    }
  }

  #pragma unroll
  for (int mi = 0; mi < 2; mi++){
    #pragma unroll
    for (int ni = 0; ni < 4; ni++){
      int col = bn + wn + ni*8 + kq;
      if (col >= Ntot) continue;
      float bx = 0.f, by = 0.f;
      if (bias){ bx = bias[col]; by = bias[col+1]; }
      int row0 = bm + wm + mi*16 + r;
      if (row0 < Mr){
        int cr = Cidx ? Cidx[row0] : row0;
        float2 v = make_float2(c[mi][ni][0] + bx, c[mi][ni][1] + by);
        *(float2*)(C + (size_t)cr*Ntot + col) = v;
      }
      if (row0 + 8 < Mr){
        int cr = Cidx ? Cidx[row0+8] : row0+8;
        float2 v = make_float2(c[mi][ni][2] + bx, c[mi][ni][3] + by);
        *(float2*)(C + (size_t)cr*Ntot + col) = v;
      }
    }
  }
}

// ---- fc_node HMMA GEMM: B from f32 [K][N], split on the fly; ldmatrix loads ----
__global__ void __launch_bounds__(256, 2)
k_hgemm_fcn(const bf16* __restrict__ Ah, const bf16* __restrict__ Al,
            const float* __restrict__ Bf, const float* __restrict__ bias,
            float* __restrict__ C, int M, int Ntot, int K){
  __shared__ bf16 sAh[128][24], sAl[128][24], sBh[64][24], sBl[64][24];
  int tid = threadIdx.x, warp = tid >> 5, lane = tid & 31;
  int bm = 0;
  int bn = blockIdx.x*64;
  int wm = (warp >> 1)*32, wn = (warp & 1)*32;

  float c[2][4][4];
  #pragma unroll
  for (int mi = 0; mi < 2; mi++)
    #pragma unroll
    for (int ni = 0; ni < 4; ni++)
      #pragma unroll
      for (int q = 0; q < 4; q++) c[mi][ni][q] = 0.f;

  int arow = tid >> 1, au = (tid & 1) << 3;
  const bf16* pAh = Ah + (size_t)arow*K;
  const bf16* pAl = Al + (size_t)arow*K;
  int bk = tid >> 4, bn4 = (tid & 15) << 2;
  bool bok = (bn + bn4 < Ntot);

  int nk = K >> 4;
  uint4 vAh, vAl;
  float4 vB = make_float4(0.f,0.f,0.f,0.f);
  vAh = *(const uint4*)(pAh + au);
  vAl = *(const uint4*)(pAl + au);
  if (bok) vB = *(const float4*)(Bf + (size_t)bk*Ntot + bn + bn4);
  *(uint4*)&sAh[arow][au] = vAh;
  *(uint4*)&sAl[arow][au] = vAl;
  {
    float bvals[4] = {vB.x, vB.y, vB.z, vB.w};
    #pragma unroll
    for (int i = 0; i < 4; i++)
      bsplit(bvals[i], &sBh[bn4 + i][bk], &sBl[bn4 + i][bk]);
  }
  __syncthreads();

  int r = lane >> 2, kq = (lane & 3) << 1;
  int lq = lane & 7, ts = lane >> 3;
  int aro = lq + ((ts & 1) ? 8 : 0);
  int aco = (ts & 2) ? 8 : 0;
  int bro = lq + ((ts & 2) ? 8 : 0);
  int bco = (ts & 1) ? 8 : 0;
  for (int kc = 0; kc < nk; kc++){
    bool more = (kc + 1 < nk);
    if (more){
      int k0 = (kc + 1) << 4;
      vAh = *(const uint4*)(pAh + k0 + au);
      vAl = *(const uint4*)(pAl + k0 + au);
      vB = make_float4(0.f,0.f,0.f,0.f);
      if (bok) vB = *(const float4*)(Bf + (size_t)(k0 + bk)*Ntot + bn + bn4);
    }
    uint32_t fah[2][4], fal[2][4], fbh[4][2], fbl[4][2];
    #pragma unroll
    for (int mi = 0; mi < 2; mi++){
      int rb = wm + mi*16 + aro;
      ldsm_x4(fah[mi], &sAh[rb][aco]);
      ldsm_x4(fal[mi], &sAl[rb][aco]);
    }
    #pragma unroll
    for (int np = 0; np < 2; np++){
      int nb = wn + np*16 + bro;
      uint32_t th[4], tl[4];
      ldsm_x4(th, &sBh[nb][bco]);
      ldsm_x4(tl, &sBl[nb][bco]);
      fbh[np*2  ][0] = th[0]; fbh[np*2  ][1] = th[1];
      fbh[np*2+1][0] = th[2]; fbh[np*2+1][1] = th[3];
      fbl[np*2  ][0] = tl[0]; fbl[np*2  ][1] = tl[1];
      fbl[np*2+1][0] = tl[2]; fbl[np*2+1][1] = tl[3];
    }
    #pragma unroll
    for (int mi = 0; mi < 2; mi++)
      #pragma unroll
      for (int ni = 0; ni < 4; ni++){
        MMA_BF16(c[mi][ni], fah[mi], fbh[ni]);
        MMA_BF16(c[mi][ni], fah[mi], fbl[ni]);
        MMA_BF16(c[mi][ni], fal[mi], fbh[ni]);
      }
    if (more){
      __syncthreads();
      *(uint4*)&sAh[arow][au] = vAh;
      *(uint4*)&sAl[arow][au] = vAl;
      float bvals[4] = {vB.x, vB.y, vB.z, vB.w};
      #pragma unroll
      for (int i = 0; i < 4; i++)
        bsplit(bvals[i], &sBh[bn4 + i][bk], &sBl[bn4 + i][bk]);
      __syncthreads();
    }
  }

  #pragma unroll
  for (int mi = 0; mi < 2; mi++){
    #pragma unroll
    for (int ni = 0; ni < 4; ni++){
      int col = bn + wn + ni*8 + kq;
      if (col >= Ntot) continue;
      float bx = bias[col], by = bias[col+1];
      int row0 = bm + wm + mi*16 + r;
      float2 v0 = make_float2(c[mi][ni][0] + bx, c[mi][ni][1] + by);
      *(float2*)(C + (size_t)row0*Ntot + col) = v0;
      float2 v1 = make_float2(c[mi][ni][2] + bx, c[mi][ni][3] + by);
      *(float2*)(C + (size_t)(row0+8)*Ntot + col) = v1;
    }
  }
}

// ---------------- scalar SGEMM (fc_sp only) ----------------
__global__ void k_gemm(const float* __restrict__ A, const float* __restrict__ B,
                       const float* __restrict__ bias, float* __restrict__ C,
                       int M, int N, int K){
  __shared__ float As[16][64];
  __shared__ float Bs[16][64];
  int bn = blockIdx.x*64, bm = blockIdx.y*64;
  int tid = threadIdx.x;
  int tx = tid & 15, ty = tid >> 4;
  float acc[4][4];
  #pragma unroll
  for (int i = 0; i < 4; i++)
    #pragma unroll
    for (int j = 0; j < 4; j++) acc[i][j] = 0.f;
  int ar = tid >> 2, ak = (tid & 3) << 2;
  int bk = tid >> 4, bn2 = (tid & 15) << 2;
  for (int k0 = 0; k0 < K; k0 += 16){
    float4 av = make_float4(0.f,0.f,0.f,0.f);
    if (bm + ar < M) av = *(const float4*)(A + (size_t)(bm + ar)*K + k0 + ak);
    As[ak  ][ar] = av.x; As[ak+1][ar] = av.y; As[ak+2][ar] = av.z; As[ak+3][ar] = av.w;
    float4 bv = make_float4(0.f,0.f,0.f,0.f);
    if (bn + bn2 < N) bv = *(const float4*)(B + (size_t)(k0 + bk)*N + bn + bn2);
    *(float4*)&Bs[bk][bn2] = bv;
    __syncthreads();
    #pragma unroll
    for (int kk = 0; kk < 16; kk++){
      float4 ra = *(const float4*)&As[kk][ty << 2];
      float4 rb = *(const float4*)&Bs[kk][tx << 2];
      acc[0][0] += ra.x*rb.x; acc[0][1] += ra.x*rb.y; acc[0][2] += ra.x*rb.z; acc[0][3] += ra.x*rb.w;
      acc[1][0] += ra.y*rb.x; acc[1][1] += ra.y*rb.y; acc[1][2] += ra.y*rb.z; acc[1][3] += ra.y*rb.w;
      acc[2][0] += ra.z*rb.x; acc[2][1] += ra.z*rb.y; acc[2][2] += ra.z*rb.z; acc[2][3] += ra.z*rb.w;
      acc[3][0] += ra.w*rb.x; acc[3][1] += ra.w*rb.y; acc[3][2] += ra.w*rb.z; acc[3][3] += ra.w*rb.w;
    }
    __syncthreads();
  }
  #pragma unroll
  for (int i = 0; i < 4; i++){
    int row = bm + (ty << 2) + i;
    if (row >= M) continue;
    #pragma unroll
    for (int j = 0; j < 4; j++){
      int col = bn + (tx << 2) + j;
      if (col >= N) continue;
      float v = acc[i][j];
      if (bias) v += bias[col];
      C[(size_t)row*N + col] = v;
    }
  }
}

// ---------------- attention dots ----------------
__global__ void k_attdot1(const float* __restrict__ aw_s, const float* __restrict__ aw_d){
  int i = blockIdx.x*256 + threadIdx.x;
  if (i >= NN*4) return;
  int n = i >> 2, h = i & 3;
  const float4* hp = (const float4*)(g_h1 + n*256 + h*64);
  const float4* sw = (const float4*)(aw_s + h*64);
  const float4* dw = (const float4*)(aw_d + h*64);
  float s = 0.f, d = 0.f;
  #pragma unroll
  for (int j = 0; j < 16; j++){
    float4 x = hp[j], a = sw[j], b = dw[j];
    s += x.x*a.x + x.y*a.y + x.z*a.z + x.w*a.w;
    d += x.x*b.x + x.y*b.y + x.z*b.z + x.w*b.w;
  }
  g_as1[i] = s; g_ad1[i] = d;
}
__global__ void k_attdot2(const float* __restrict__ aw_s, const float* __restrict__ aw_d){
  int n = blockIdx.x*256 + threadIdx.x;
  if (n >= NN) return;
  const float4* hp = (const float4*)(g_h2 + n*128);
  const float4* sw = (const float4*)aw_s;
  const float4* dw = (const float4*)aw_d;
  float s = 0.f, d = 0.f;
  #pragma unroll
  for (int j = 0; j < 32; j++){
    float4 x = hp[j], a = sw[j], b = dw[j];
    s += x.x*a.x + x.y*a.y + x.z*a.z + x.w*a.w;
    d += x.x*b.x + x.y*b.y + x.z*b.z + x.w*b.w;
  }
  g_as2[n] = s; g_ad2[n] = d;
}

// ---------------- edge softmax + aggregation, layer 1 -> z1 bf16 split ----------------
__global__ void k_agg1(const float* __restrict__ bias){
  int wid = threadIdx.x >> 5, lane = threadIdx.x & 31;
  int n = blockIdx.x*8 + wid;
  int r0 = g_rowptr[n], r1 = g_rowptr[n+1];
  float4 ad = *(const float4*)(g_ad1 + n*4);
  float m0 = -1e30f, m1 = -1e30f, m2 = -1e30f, m3 = -1e30f;
  for (int e = r0 + lane; e < r1; e += 32){
    int s = g_srcs[e];
    float4 as = *(const float4*)(g_as1 + s*4);
    float v0 = as.x + ad.x; v0 = v0 > 0.f ? v0 : 0.2f*v0;
    float v1 = as.y + ad.y; v1 = v1 > 0.f ? v1 : 0.2f*v1;
    float v2 = as.z + ad.z; v2 = v2 > 0.f ? v2 : 0.2f*v2;
    float v3 = as.w + ad.w; v3 = v3 > 0.f ? v3 : 0.2f*v3;
    m0 = fmaxf(m0, v0); m1 = fmaxf(m1, v1); m2 = fmaxf(m2, v2); m3 = fmaxf(m3, v3);
  }
  #pragma unroll
  for (int o = 16; o; o >>= 1){
    m0 = fmaxf(m0, __shfl_xor_sync(0xffffffffu, m0, o));
    m1 = fmaxf(m1, __shfl_xor_sync(0xffffffffu, m1, o));
    m2 = fmaxf(m2, __shfl_xor_sync(0xffffffffu, m2, o));
    m3 = fmaxf(m3, __shfl_xor_sync(0xffffffffu, m3, o));
  }
  float s0 = 0.f, s1 = 0.f, s2 = 0.f, s3 = 0.f;
  for (int e = r0 + lane; e < r1; e += 32){
    int s = g_srcs[e];
    float4 as = *(const float4*)(g_as1 + s*4);
    float v0 = as.x + ad.x; v0 = v0 > 0.f ? v0 : 0.2f*v0;
    float v1 = as.y + ad.y; v1 = v1 > 0.f ? v1 : 0.2f*v1;
    float v2 = as.z + ad.z; v2 = v2 > 0.f ? v2 : 0.2f*v2;
    float v3 = as.w + ad.w; v3 = v3 > 0.f ? v3 : 0.2f*v3;
    s0 += __expf(v0 - m0); s1 += __expf(v1 - m1);
    s2 += __expf(v2 - m2); s3 += __expf(v3 - m3);
  }
  #pragma unroll
  for (int o = 16; o; o >>= 1){
    s0 += __shfl_xor_sync(0xffffffffu, s0, o);
    s1 += __shfl_xor_sync(0xffffffffu, s1, o);
    s2 += __shfl_xor_sync(0xffffffffu, s2, o);
    s3 += __shfl_xor_sync(0xffffffffu, s3, o);
  }
  int hsel = lane >> 3;
  float mh  = hsel == 0 ? m0 : hsel == 1 ? m1 : hsel == 2 ? m2 : m3;
  float inv = 1.f / (hsel == 0 ? s0 : hsel == 1 ? s1 : hsel == 2 ? s2 : s3);
  float adh = hsel == 0 ? ad.x : hsel == 1 ? ad.y : hsel == 2 ? ad.z : ad.w;
  float a0=0,a1=0,a2=0,a3=0,a4=0,a5=0,a6=0,a7=0;
  for (int e = r0; e < r1; e++){
    int s = g_srcs[e];
    float v = g_as1[s*4 + hsel] + adh; v = v > 0.f ? v : 0.2f*v;
    float alpha = __expf(v - mh) * inv;
    const float4* xp = (const float4*)(g_h1 + s*256 + lane*8);
    float4 x0 = xp[0], x1 = xp[1];
    a0 += alpha*x0.x; a1 += alpha*x0.y; a2 += alpha*x0.z; a3 += alpha*x0.w;
    a4 += alpha*x1.x; a5 += alpha*x1.y; a6 += alpha*x1.z; a7 += alpha*x1.w;
  }
  int cb = lane*8;
  float r[8] = {a0,a1,a2,a3,a4,a5,a6,a7};
  #pragma unroll
  for (int i = 0; i < 8; i++){
    float o = r[i] + bias[cb + i];
    o = o > 0.f ? o : expm1f(o);                           // ELU
    bsplit(o, &g_z1h[n*256 + cb + i], &g_z1l[n*256 + cb + i]);
  }
}

// ---------------- edge softmax + aggregation, layer 2 -> z2 bf16 split ----------------
__global__ void k_agg2(const float* __restrict__ bias){
  int wid = threadIdx.x >> 5, lane = threadIdx.x & 31;
  int n = blockIdx.x*8 + wid;
  int r0 = g_rowptr[n], r1 = g_rowptr[n+1];
  float ad = g_ad2[n];
  float m = -1e30f;
  for (int e = r0 + lane; e < r1; e += 32){
    float v = g_as2[g_srcs[e]] + ad; v = v > 0.f ? v : 0.2f*v;
    m = fmaxf(m, v);
  }
  #pragma unroll
  for (int o = 16; o; o >>= 1) m = fmaxf(m, __shfl_xor_sync(0xffffffffu, m, o));
  float ssum = 0.f;
  for (int e = r0 + lane; e < r1; e += 32){
    float v = g_as2[g_srcs[e]] + ad; v = v > 0.f ? v : 0.2f*v;
    ssum += __expf(v - m);
  }
  #pragma unroll
  for (int o = 16; o; o >>= 1) ssum += __shfl_xor_sync(0xffffffffu, ssum, o);
  float inv = 1.f / ssum;
  float a0=0,a1=0,a2=0,a3=0;
  for (int e = r0; e < r1; e++){
    int s = g_srcs[e];
    float v = g_as2[s] + ad; v = v > 0.f ? v : 0.2f*v;
    float alpha = __expf(v - m) * inv;
    float4 x = *(const float4*)(g_h2 + s*128 + lane*4);
    a0 += alpha*x.x; a1 += alpha*x.y; a2 += alpha*x.z; a3 += alpha*x.w;
  }
  int cb = lane*4;
  float rr[4] = {a0 + bias[cb], a1 + bias[cb+1], a2 + bias[cb+2], a3 + bias[cb+3]};
  #pragma unroll
  for (int i = 0; i < 4; i++)
    bsplit(rr[i], &g_z2h[n*128 + cb + i], &g_z2l[n*128 + cb + i]);
}

// ---------------- BiLSTM recurrence (x prefetch pipeline) ----------------
__global__ void __launch_bounds__(512, 1)
k_lstm(const float* __restrict__ whhf, const float* __restrict__ whhb,
       const int* __restrict__ lengths){
  extern __shared__ char smraw[];
  ull*   ws  = (ull*)smraw;
  float* hsm = (float*)(ws + 512*33);
  float* gsm = hsm + 256;
  int g   = threadIdx.x;
  int dir = blockIdx.y;
  int b0  = blockIdx.x*2;
  const float* whh = dir ? whhb : whhf;
  const ull* wrow = (const ull*)(whh + g*128);
  ull wreg[32];
  #pragma unroll
  for (int j = 0; j < 32; j++) wreg[j] = wrow[j];
  #pragma unroll
  for (int j = 0; j < 32; j++) ws[g*33 + j] = wrow[32 + j];
  if (g < 256) hsm[g] = 0.f;
  float cc = 0.f;
  int len0 = lengths[b0], len1 = lengths[b0+1];
  int Tn = len0 > len1 ? len0 : len1;
  const float* x0p = g_xproj[dir] + (size_t)b0*TT*512;
  const float* x1p = x0p + (size_t)TT*512;
  float xv0 = x0p[g];
  float xv1 = x1p[g];
  __syncthreads();
  for (int t = 0; t < Tn; t++){
    float nxv0 = 0.f, nxv1 = 0.f;
    if (t + 1 < Tn){                         // prefetch next step's x
      nxv0 = x0p[(t+1)*512 + g];
      nxv1 = x1p[(t+1)*512 + g];
    }
    ull a0 = 0ULL, a1 = 0ULL;
    const ull* h0p = (const ull*)hsm;
    const ull* h1p = (const ull*)(hsm + 128);
    #pragma unroll
    for (int j = 0; j < 32; j++){
      ull w = wreg[j];
      a0 = fma2(w, h0p[j], a0);
      a1 = fma2(w, h1p[j], a1);
    }
    #pragma unroll
    for (int j = 0; j < 32; j++){
      ull w = ws[g*33 + j];
      a0 = fma2(w, h0p[32 + j], a0);
      a1 = fma2(w, h1p[32 + j], a1);
    }
    gsm[g]       = hsum2(a0) + xv0;
    gsm[512 + g] = hsum2(a1) + xv1;
    __syncthreads();
    if (g < 256){
      int b = g >> 7, j = g & 127;
      const float* gb = gsm + b*512;
      float gi = gb[j], gf = gb[128 + j], gg = gb[256 + j], go = gb[384 + j];
      cc = sigf(gf)*cc + sigf(gi)*tanhf(gg);
      float h = sigf(go)*tanhf(cc);
      hsm[b*128 + j] = h;
      int L = b ? len1 : len0;
      if (dir == 0){
        if (t < L) g_lstm[((size_t)(b0 + b)*TT + t)*256 + j] = h;
      } else {
        if (t < L) g_lstm[((size_t)(b0 + b)*TT + (L - 1 - t))*256 + 128 + j] = h;
      }
    }
    __syncthreads();
    xv0 = nxv0; xv1 = nxv1;
  }
}

// ---------------- masked attention pooling ----------------
__global__ void k_attnpool(const float* __restrict__ wn, const float* __restrict__ bn,
                           const float* __restrict__ wsp, const float* __restrict__ bsp,
                           const int* __restrict__ lengths){
  __shared__ float sc[256];
  __shared__ float red[256];
  int b = blockIdx.x, p = blockIdx.y;
  const float* w = p ? wsp : wn;
  float bias = p ? bsp[0] : bn[0];
  int tid = threadIdx.x;
  int len = lengths[b];
  float sv = -1e30f;
  if (tid < TT && tid < len){
    const float4* row = (const float4*)(g_lstm + ((size_t)b*TT + tid)*256);
    const float4* wv = (const float4*)w;
    float s = 0.f;
    #pragma unroll
    for (int j = 0; j < 64; j++){
      float4 x = row[j], y = wv[j];
      s += x.x*y.x + x.y*y.y + x.z*y.z + x.w*y.w;
    }
    sv = s + bias;
  }
  red[tid] = sv;
  __syncthreads();
  #pragma unroll
  for (int o = 128; o; o >>= 1){ if (tid < o) red[tid] = fmaxf(red[tid], red[tid+o]); __syncthreads(); }
  float m = red[0];
  __syncthreads();
  float e = (sv <= -1e29f) ? 0.f : __expf(sv - m);
  sc[tid] = e; red[tid] = e;
  __syncthreads();
  #pragma unroll
  for (int o = 128; o; o >>= 1){ if (tid < o) red[tid] += red[tid+o]; __syncthreads(); }
  float inv = 1.f / red[0];
  float acc = 0.f;
  for (int t = 0; t < TT; t++)
    acc += sc[t] * g_lstm[((size_t)b*TT + t)*256 + tid];
  float v = acc * inv;
  g_ctx[p][b*256 + tid] = v;
  if (p == 0) bsplit(v, &g_cxh[b*256 + tid], &g_cxl[b*256 + tid]);
}

// ---------------- launch ----------------
extern "C" void kernel_launch(void* const* d_in, const int* in_sizes, int n_in,
                              void* d_out, int out_size){
  const float* xc   = (const float*)d_in[0];
  const float* tf   = (const float*)d_in[1];
  const float* emb  = (const float*)d_in[2];
  const float* g1W  = (const float*)d_in[3];
  const float* g1as = (const float*)d_in[4];
  const float* g1ad = (const float*)d_in[5];
  const float* g1b  = (const float*)d_in[6];
  const float* g2W  = (const float*)d_in[7];
  const float* g2as = (const float*)d_in[8];
  const float* g2ad = (const float*)d_in[9];
  const float* g2b  = (const float*)d_in[10];
  const float* wihf = (const float*)d_in[11];
  const float* whhf = (const float*)d_in[12];
  const float* bf   = (const float*)d_in[13];
  const float* wihb = (const float*)d_in[14];
  const float* whhb = (const float*)d_in[15];
  const float* bb   = (const float*)d_in[16];
  const float* anw  = (const float*)d_in[17];
  const float* anb  = (const float*)d_in[18];
  const float* asw  = (const float*)d_in[19];
  const float* asb  = (const float*)d_in[20];
  const float* fnW  = (const float*)d_in[21];
  const float* fnb  = (const float*)d_in[22];
  const float* fsW  = (const float*)d_in[23];
  const float* fsb  = (const float*)d_in[24];
  const int*   ei   = (const int*)d_in[25];
  const int*   seq  = (const int*)d_in[26];
  const int*   len  = (const int*)d_in[27];
  float* out = (float*)d_out;

  float *p_h1, *p_h2, *p_xp, *p_ctx, *p_lstm;
  int *p_af, *p_ab, *p_ci;
  bf16 *p_nfh, *p_nfl, *p_w1h, *p_w1l, *p_z1h, *p_z1l, *p_w2h, *p_w2l;
  bf16 *p_z2h, *p_z2l, *p_wih, *p_cxh, *p_cxl;
  cudaGetSymbolAddress((void**)&p_h1,  g_h1);
  cudaGetSymbolAddress((void**)&p_h2,  g_h2);
  cudaGetSymbolAddress((void**)&p_xp,  g_xproj);
  cudaGetSymbolAddress((void**)&p_ctx, g_ctx);
  cudaGetSymbolAddress((void**)&p_lstm, g_lstm);
  cudaGetSymbolAddress((void**)&p_af,  g_aidxf);
  cudaGetSymbolAddress((void**)&p_ab,  g_aidxb);
  cudaGetSymbolAddress((void**)&p_ci,  g_cidx);
  cudaGetSymbolAddress((void**)&p_nfh, g_nfh);
  cudaGetSymbolAddress((void**)&p_nfl, g_nfl);
  cudaGetSymbolAddress((void**)&p_w1h, g_w1h);
  cudaGetSymbolAddress((void**)&p_w1l, g_w1l);
  cudaGetSymbolAddress((void**)&p_z1h, g_z1h);
  cudaGetSymbolAddress((void**)&p_z1l, g_z1l);
  cudaGetSymbolAddress((void**)&p_w2h, g_w2h);
  cudaGetSymbolAddress((void**)&p_w2l, g_w2l);
  cudaGetSymbolAddress((void**)&p_z2h, g_z2h);
  cudaGetSymbolAddress((void**)&p_z2l, g_z2l);
  cudaGetSymbolAddress((void**)&p_wih, g_wih);
  cudaGetSymbolAddress((void**)&p_cxh, g_cxh);
  cudaGetSymbolAddress((void**)&p_cxl, g_cxl);

  int lstm_smem = 512*33*8 + 256*4 + 1024*4;
  cudaFuncSetAttribute(k_lstm, cudaFuncAttributeMaxDynamicSharedMemorySize, lstm_smem);

  // fork a side stream for the independent CSR/index chain (capture-legal pattern)
  cudaStream_t s2;
  cudaStreamCreateWithFlags(&s2, cudaStreamNonBlocking);
  cudaEvent_t evFork, evJoin, evCtx, evTail;
  cudaEventCreateWithFlags(&evFork, cudaEventDisableTiming);
  cudaEventCreateWithFlags(&evJoin, cudaEventDisableTiming);
  cudaEventCreateWithFlags(&evCtx,  cudaEventDisableTiming);
  cudaEventCreateWithFlags(&evTail, cudaEventDisableTiming);
  cudaEventRecord(evFork, 0);
  cudaStreamWaitEvent(s2, evFork, 0);

  // side stream: CSR build + sequence indexing + lstm zero
  k_zero_cnt<<<(NN+255)/256, 256, 0, s2>>>();
  k_count<<<(ET+255)/256, 256, 0, s2>>>(ei);
  k_scan<<<1, 1024, 0, s2>>>();
  k_scatter<<<(ET+255)/256, 256, 0, s2>>>(ei);
  k_sortseg<<<2500, 256, 0, s2>>>(ei);
  k_seqidx<<<BB, 256, 0, s2>>>(seq, len);
  cudaMemsetAsync(p_lstm, 0, (size_t)BB*TT*256*sizeof(float), s2);

  // main stream: prep + weight splits + GAT1 GEMM + attdot1
  k_prep<<<11250, 256>>>(xc, tf, emb, wihf, wihb);
  k_tsplit<<<dim3(8, 5),  dim3(32,32)>>>(g1W, p_w1h, p_w1l, 134, 256, 144);
  k_tsplit<<<dim3(4, 8),  dim3(32,32)>>>(g2W, p_w2h, p_w2l, 256, 128, 256);
  k_hgemm<<<dim3(4, 157), 256>>>(p_nfh, p_nfl, p_w1h, p_w1l,
      nullptr, p_h1, NN, 256, 144, nullptr, nullptr, 0);
  k_attdot1<<<(NN*4+255)/256, 256>>>(g1as, g1ad);

  // join: agg1 needs both branches
  cudaEventRecord(evJoin, s2);
  cudaStreamWaitEvent(0, evJoin, 0);

  k_agg1<<<2500, 256>>>(g1b);

  // GAT layer 2
  k_hgemm<<<dim3(2, 157), 256>>>(p_z1h, p_z1l, p_w2h, p_w2l,
      nullptr, p_h2, NN, 128, 256, nullptr, nullptr, 0);
  k_attdot2<<<(NN+255)/256, 256>>>(g2as, g2ad);
  k_agg2<<<2500, 256>>>(g2b);

  // x-projections over valid rows
  k_hgemm<<<dim3(8, 200), 256>>>(p_z2h, p_z2l, p_wih,             p_wih + 512*128,
      bf, p_xp,                      BB*TT, 512, 128, p_af, p_ci, 1);
  k_hgemm<<<dim3(8, 200), 256>>>(p_z2h, p_z2l, p_wih + 2*512*128, p_wih + 3*512*128,
      bb, p_xp + (size_t)BB*TT*512,  BB*TT, 512, 128, p_ab, p_ci, 1);

  // BiLSTM
  k_lstm<<<dim3(64, 2), 512, lstm_smem>>>(whhf, whhb, len);

  // attention pooling
  k_attnpool<<<dim3(BB, 2), 256>>>(anw, anb, asw, asb, len);

  // output heads: fc_sp on side stream (concurrent with fc_node)
  cudaEventRecord(evCtx, 0);
  cudaStreamWaitEvent(s2, evCtx, 0);
  k_gemm<<<dim3(1, 2), 256, 0, s2>>>(p_ctx + BB*256, fsW, fsb, out + (size_t)BB*20000, BB, 64, 256);
  k_hgemm_fcn<<<313, 256>>>(p_cxh, p_cxl, fnW, fnb, out, BB, 20000, 256);
  cudaEventRecord(evTail, s2);
  cudaStreamWaitEvent(0, evTail, 0);

  cudaEventDestroy(evFork);
  cudaEventDestroy(evJoin);
  cudaEventDestroy(evCtx);
  cudaEventDestroy(evTail);
  cudaStreamDestroy(s2);
}